// round 1
// baseline (speedup 1.0000x reference)
#include <cuda_runtime.h>
#include <math.h>

#define BATCH 256
#define S 200
#define D 192
#define NH 6
#define DH 32
#define NL 3
#define FF 576
#define RD 199
#define MTOT (BATCH*S)

// ---------------- scratch (device globals; no runtime allocation) ----------
__device__ float g_h[MTOT*D];        // residual stream [B,S,D]
__device__ float g_att[MTOT*D];      // attention output [B,S,D]
__device__ float g_q[MTOT*D];        // [B,H,S,Dh]
__device__ float g_k[MTOT*D];
__device__ float g_v[MTOT*D];
__device__ float g_ff[MTOT*FF];      // FFN hidden [B*S,FF]
__device__ float g_pool[BATCH*D];    // pooled attention (pre-proj)
__device__ float g_pooled[BATCH*D];  // pooled (post-proj)

__device__ __forceinline__ float gelu_exact(float x) {
    return 0.5f * x * (1.0f + erff(x * 0.70710678118654752f));
}

// ---------------- kernel 1: per-ROI linear + LN + GELU + pos --------------
// grid (200, 32), 192 threads. Block: fixed roi r, 8 batch rows, full D.
__global__ void roi_tok_kernel(const float* __restrict__ x,
                               const float* __restrict__ W,
                               const float* __restrict__ bias,
                               const float* __restrict__ lng,
                               const float* __restrict__ lnb,
                               const float* __restrict__ pos,
                               float* __restrict__ out)
{
    int r  = blockIdx.x;
    int b0 = blockIdx.y * 8;
    int d  = threadIdx.x;              // 0..191
    __shared__ float xs[8 * RD];
    __shared__ float buf[8][D + 1];

    for (int i = d; i < 8 * RD; i += D) {
        int j = i / RD, k = i % RD;
        xs[i] = x[(size_t)(b0 + j) * (200 * RD) + r * RD + k];
    }
    __syncthreads();

    float acc[8] = {0, 0, 0, 0, 0, 0, 0, 0};
    const float* wp = W + (size_t)r * RD * D + d;
    for (int k = 0; k < RD; ++k) {
        float w = wp[(size_t)k * D];
#pragma unroll
        for (int j = 0; j < 8; ++j) acc[j] += xs[j * RD + k] * w;
    }
    float bb = bias[r * D + d];
#pragma unroll
    for (int j = 0; j < 8; ++j) buf[j][d] = acc[j] + bb;
    __syncthreads();

    int wid = d >> 5, lane = d & 31;
    for (int j = wid; j < 8; j += 6) {
        float sum = 0.f, sq = 0.f;
#pragma unroll
        for (int i = 0; i < 6; ++i) { float v = buf[j][lane + 32 * i]; sum += v; sq += v * v; }
#pragma unroll
        for (int o = 16; o > 0; o >>= 1) {
            sum += __shfl_xor_sync(0xffffffffu, sum, o);
            sq  += __shfl_xor_sync(0xffffffffu, sq,  o);
        }
        float mean = sum * (1.f / D);
        float rstd = rsqrtf(sq * (1.f / D) - mean * mean + 1e-5f);
#pragma unroll
        for (int i = 0; i < 6; ++i) {
            int c = lane + 32 * i;
            float v = (buf[j][c] - mean) * rstd * lng[r * D + c] + lnb[r * D + c];
            v = gelu_exact(v) + pos[r * D + c];
            out[((size_t)(b0 + j) * S + r) * D + c] = v;
        }
    }
}

// ---------------- kernel 2: [M,192] x [192,576] tiled GEMM -----------------
// mode 0: W = [3,192,192] QKV stack, scatter to q/k/v [B,H,S,Dh]
// mode 1: W = [192,576] row-major, GELU epilogue into of
// grid (800, 9), 256 threads. BM=BN=64, BK=16, 4x4 microtile.
__global__ void gemm576_kernel(const float* __restrict__ A,
                               const float* __restrict__ W,
                               const float* __restrict__ bias,
                               float* __restrict__ oq, float* __restrict__ ok,
                               float* __restrict__ ov, float* __restrict__ of,
                               int mode)
{
    __shared__ float As[16][65];
    __shared__ float Bs[16][65];
    int m0 = blockIdx.x * 64, n0 = blockIdx.y * 64;
    int t = threadIdx.x;
    int tr = t >> 4, tc = t & 15;
    float acc[4][4] = {};

    for (int k0 = 0; k0 < D; k0 += 16) {
#pragma unroll
        for (int i = t; i < 1024; i += 256) {
            int r = i >> 4, kk = i & 15;
            As[kk][r] = A[(size_t)(m0 + r) * D + k0 + kk];
        }
#pragma unroll
        for (int i = t; i < 1024; i += 256) {
            int kk = i >> 6, c = i & 63;
            int n = n0 + c;
            size_t idx = (mode == 0)
                ? ((size_t)(n / D) * D * D + (size_t)(k0 + kk) * D + (n % D))
                : ((size_t)(k0 + kk) * FF + n);
            Bs[kk][c] = W[idx];
        }
        __syncthreads();
#pragma unroll
        for (int kk = 0; kk < 16; ++kk) {
            float a[4], bv[4];
#pragma unroll
            for (int i = 0; i < 4; ++i) a[i] = As[kk][tr * 4 + i];
#pragma unroll
            for (int j = 0; j < 4; ++j) bv[j] = Bs[kk][tc * 4 + j];
#pragma unroll
            for (int i = 0; i < 4; ++i)
#pragma unroll
                for (int j = 0; j < 4; ++j) acc[i][j] += a[i] * bv[j];
        }
        __syncthreads();
    }

#pragma unroll
    for (int i = 0; i < 4; ++i) {
        int m = m0 + tr * 4 + i;
        int b = m / S, s = m % S;
#pragma unroll
        for (int j = 0; j < 4; ++j) {
            int n = n0 + tc * 4 + j;
            float v = acc[i][j] + bias[n];
            if (mode == 0) {
                int which = n / D, rem = n % D;
                int hd = rem >> 5, dh = rem & 31;
                float* o = (which == 0) ? oq : ((which == 1) ? ok : ov);
                o[(((size_t)b * NH + hd) * S + s) * DH + dh] = v;
            } else {
                of[(size_t)m * FF + n] = gelu_exact(v);
            }
        }
    }
}

// ---------------- kernel 3: attention, one block per (b,h) -----------------
// V in smem (25.6KB), K streamed (uniform/broadcast loads). 1 thread = 1 query.
__global__ void attn_kernel(const float* __restrict__ q,
                            const float* __restrict__ k,
                            const float* __restrict__ v,
                            float* __restrict__ out)
{
    __shared__ float Vs[S * DH];
    int bh = blockIdx.x;
    int b = bh / NH, hd = bh % NH;
    const float* kb = k + (size_t)bh * S * DH;
    const float* vb = v + (size_t)bh * S * DH;
    int t = threadIdx.x;
    for (int i = t; i < S * DH; i += 256) Vs[i] = vb[i];
    __syncthreads();
    if (t < S) {
        float qv[DH];
        const float* qp = q + (size_t)bh * S * DH + t * DH;
#pragma unroll
        for (int i = 0; i < DH; ++i) qv[i] = qp[i] * 0.17677669529663687f;
        float mx = -1e30f;
        for (int s = 0; s < S; ++s) {
            float sc = 0.f;
#pragma unroll
            for (int i = 0; i < DH; ++i) sc += qv[i] * kb[s * DH + i];
            mx = fmaxf(mx, sc);
        }
        float l = 0.f;
        float o[DH] = {};
        for (int s = 0; s < S; ++s) {
            float sc = 0.f;
#pragma unroll
            for (int i = 0; i < DH; ++i) sc += qv[i] * kb[s * DH + i];
            float e = __expf(sc - mx);
            l += e;
#pragma unroll
            for (int i = 0; i < DH; ++i) o[i] += e * Vs[s * DH + i];
        }
        float inv = 1.f / l;
        float* op = out + ((size_t)b * S + t) * D + hd * DH;
#pragma unroll
        for (int i = 0; i < DH; ++i) op[i] = o[i] * inv;
    }
}

// ---------------- kernel 4: [M,K] x [K,192] + bias + residual + LN ---------
// grid (1600), 192 threads (thread = output column). BM=32, full 192-row LN fused.
__global__ void gemm_addln_kernel(const float* __restrict__ A,
                                  const float* __restrict__ W,
                                  const float* __restrict__ bias,
                                  const float* __restrict__ res,
                                  const float* __restrict__ lng,
                                  const float* __restrict__ lnb,
                                  float* __restrict__ out, int K)
{
    __shared__ float As[16][33];
    __shared__ float buf[32][D + 1];
    int m0 = blockIdx.x * 32;
    int d = threadIdx.x;
    float acc[32] = {};

    for (int k0 = 0; k0 < K; k0 += 16) {
        for (int i = d; i < 512; i += 192) {
            int r = i >> 4, kk = i & 15;
            As[kk][r] = A[(size_t)(m0 + r) * K + k0 + kk];
        }
        __syncthreads();
#pragma unroll
        for (int kk = 0; kk < 16; ++kk) {
            float w = W[(size_t)(k0 + kk) * D + d];
#pragma unroll
            for (int r = 0; r < 32; ++r) acc[r] += As[kk][r] * w;
        }
        __syncthreads();
    }

    float bb = bias[d];
#pragma unroll
    for (int r = 0; r < 32; ++r)
        buf[r][d] = acc[r] + bb + res[(size_t)(m0 + r) * D + d];
    __syncthreads();

    int wid = d >> 5, lane = d & 31;
    for (int r = wid; r < 32; r += 6) {
        float sum = 0.f, sq = 0.f;
#pragma unroll
        for (int i = 0; i < 6; ++i) { float v = buf[r][lane + 32 * i]; sum += v; sq += v * v; }
#pragma unroll
        for (int o = 16; o > 0; o >>= 1) {
            sum += __shfl_xor_sync(0xffffffffu, sum, o);
            sq  += __shfl_xor_sync(0xffffffffu, sq,  o);
        }
        float mean = sum * (1.f / D);
        float rstd = rsqrtf(sq * (1.f / D) - mean * mean + 1e-5f);
#pragma unroll
        for (int i = 0; i < 6; ++i) {
            int c = lane + 32 * i;
            out[(size_t)(m0 + r) * D + c] = (buf[r][c] - mean) * rstd * lng[c] + lnb[c];
        }
    }
}

// ---------------- kernel 5: pooled attention (Q=1 via linearity) -----------
__global__ void pool_attn_kernel(const float* __restrict__ q,
                                 const float* __restrict__ k,
                                 const float* __restrict__ v,
                                 float* __restrict__ out)
{
    __shared__ float qm[DH];
    __shared__ float sc[S];
    __shared__ float red[2];
    int bh = blockIdx.x;
    int b = bh / NH, hd = bh % NH;
    size_t base = (size_t)bh * S * DH;
    int t = threadIdx.x;
    if (t < DH) {
        float s = 0.f;
        for (int j = 0; j < S; ++j) s += q[base + j * DH + t];
        qm[t] = s * (1.f / S) * 0.17677669529663687f;
    }
    __syncthreads();
    if (t < S) {
        float x = 0.f;
#pragma unroll
        for (int i = 0; i < DH; ++i) x += qm[i] * k[base + t * DH + i];
        sc[t] = x;
    }
    __syncthreads();
    if (t == 0) {
        float mx = -1e30f;
        for (int s = 0; s < S; ++s) mx = fmaxf(mx, sc[s]);
        red[0] = mx;
    }
    __syncthreads();
    if (t < S) sc[t] = __expf(sc[t] - red[0]);
    __syncthreads();
    if (t == 0) {
        float l = 0.f;
        for (int s = 0; s < S; ++s) l += sc[s];
        red[1] = 1.f / l;
    }
    __syncthreads();
    if (t < DH) {
        float o = 0.f;
        for (int s = 0; s < S; ++s) o += sc[s] * v[base + s * DH + t];
        out[(size_t)b * D + hd * DH + t] = o * red[1];
    }
}

// ---------------- kernel 6: pooled projection [256,192]x[192,192] ----------
__global__ void pool_proj_kernel(const float* __restrict__ in,
                                 const float* __restrict__ W,
                                 const float* __restrict__ bias,
                                 float* __restrict__ out)
{
    __shared__ float row[D];
    int b = blockIdx.x, d = threadIdx.x;
    row[d] = in[(size_t)b * D + d];
    __syncthreads();
    float s = bias[d];
    for (int k = 0; k < D; ++k) s += row[k] * W[(size_t)k * D + d];
    out[(size_t)b * D + d] = s;
}

// ---------------- kernel 7: classifier head (LN + 3 GEMVs) -----------------
__global__ void cls_kernel(const float* __restrict__ in,
                           const float* __restrict__ g,  const float* __restrict__ bt,
                           const float* __restrict__ W1, const float* __restrict__ b1,
                           const float* __restrict__ W2, const float* __restrict__ b2,
                           const float* __restrict__ W3, const float* __restrict__ b3,
                           float* __restrict__ out)
{
    __shared__ float z[D];
    __shared__ float z1[96];
    __shared__ float z2[48];
    __shared__ float red[2];
    int b = blockIdx.x, t = threadIdx.x;
    float v = in[(size_t)b * D + t];
    z[t] = v;
    __syncthreads();
    if (t == 0) {
        float s = 0.f, sq = 0.f;
        for (int i = 0; i < D; ++i) { s += z[i]; sq += z[i] * z[i]; }
        float m = s / D;
        red[0] = m;
        red[1] = rsqrtf(sq / D - m * m + 1e-5f);
    }
    __syncthreads();
    z[t] = (v - red[0]) * red[1] * g[t] + bt[t];
    __syncthreads();
    if (t < 96) {
        float a = b1[t];
        for (int k = 0; k < D; ++k) a += z[k] * W1[k * 96 + t];
        z1[t] = gelu_exact(a);
    }
    __syncthreads();
    if (t < 48) {
        float a = b2[t];
        for (int k = 0; k < 96; ++k) a += z1[k] * W2[k * 48 + t];
        z2[t] = gelu_exact(a);
    }
    __syncthreads();
    if (t < 2) {
        float a = b3[t];
        for (int k = 0; k < 48; ++k) a += z2[k] * W3[k * 2 + t];
        out[(size_t)b * 2 + t] = a;
    }
}

// ---------------- launch ----------------------------------------------------
extern "C" void kernel_launch(void* const* d_in, const int* in_sizes, int n_in,
                              void* d_out, int out_size)
{
    const float* x        = (const float*)d_in[0];
    const float* roi_W    = (const float*)d_in[1];
    const float* roi_b    = (const float*)d_in[2];
    const float* roi_lng  = (const float*)d_in[3];
    const float* roi_lnb  = (const float*)d_in[4];
    const float* pos_emb  = (const float*)d_in[5];
    const float* enc_Wqkv = (const float*)d_in[6];
    const float* enc_bqkv = (const float*)d_in[7];
    const float* enc_Wo   = (const float*)d_in[8];
    const float* enc_bo   = (const float*)d_in[9];
    const float* enc_ln1g = (const float*)d_in[10];
    const float* enc_ln1b = (const float*)d_in[11];
    const float* enc_W1   = (const float*)d_in[12];
    const float* enc_b1   = (const float*)d_in[13];
    const float* enc_W2   = (const float*)d_in[14];
    const float* enc_b2   = (const float*)d_in[15];
    const float* enc_ln2g = (const float*)d_in[16];
    const float* enc_ln2b = (const float*)d_in[17];
    const float* pool_Wqkv= (const float*)d_in[18];
    const float* pool_bqkv= (const float*)d_in[19];
    const float* pool_Wo  = (const float*)d_in[20];
    const float* pool_bo  = (const float*)d_in[21];
    const float* cls_lng  = (const float*)d_in[22];
    const float* cls_lnb  = (const float*)d_in[23];
    const float* cls_W1   = (const float*)d_in[24];
    const float* cls_b1   = (const float*)d_in[25];
    const float* cls_W2   = (const float*)d_in[26];
    const float* cls_b2   = (const float*)d_in[27];
    const float* cls_W3   = (const float*)d_in[28];
    const float* cls_b3   = (const float*)d_in[29];
    float* out = (float*)d_out;

    float *h, *att, *q, *k, *v, *ff, *pool, *pooled;
    cudaGetSymbolAddress((void**)&h,      g_h);
    cudaGetSymbolAddress((void**)&att,    g_att);
    cudaGetSymbolAddress((void**)&q,      g_q);
    cudaGetSymbolAddress((void**)&k,      g_k);
    cudaGetSymbolAddress((void**)&v,      g_v);
    cudaGetSymbolAddress((void**)&ff,     g_ff);
    cudaGetSymbolAddress((void**)&pool,   g_pool);
    cudaGetSymbolAddress((void**)&pooled, g_pooled);

    // tokenizer
    roi_tok_kernel<<<dim3(200, 32), 192>>>(x, roi_W, roi_b, roi_lng, roi_lnb, pos_emb, h);

    // encoder layers
    for (int l = 0; l < NL; ++l) {
        const float* Wqkv = enc_Wqkv + (size_t)l * 3 * D * D;
        const float* bqkv = enc_bqkv + (size_t)l * 3 * D;
        gemm576_kernel<<<dim3(MTOT / 64, 9), 256>>>(h, Wqkv, bqkv, q, k, v, nullptr, 0);
        attn_kernel<<<BATCH * NH, 256>>>(q, k, v, att);
        gemm_addln_kernel<<<MTOT / 32, 192>>>(att, enc_Wo + (size_t)l * D * D,
                                              enc_bo + l * D, h,
                                              enc_ln1g + l * D, enc_ln1b + l * D, h, D);
        gemm576_kernel<<<dim3(MTOT / 64, 9), 256>>>(h, enc_W1 + (size_t)l * D * FF,
                                                    enc_b1 + l * FF,
                                                    nullptr, nullptr, nullptr, ff, 1);
        gemm_addln_kernel<<<MTOT / 32, 192>>>(ff, enc_W2 + (size_t)l * FF * D,
                                              enc_b2 + l * D, h,
                                              enc_ln2g + l * D, enc_ln2b + l * D, h, FF);
    }

    // pooling
    gemm576_kernel<<<dim3(MTOT / 64, 9), 256>>>(h, pool_Wqkv, pool_bqkv, q, k, v, nullptr, 0);
    pool_attn_kernel<<<BATCH * NH, 256>>>(q, k, v, pool);
    pool_proj_kernel<<<BATCH, 192>>>(pool, pool_Wo, pool_bo, pooled);

    // classifier
    cls_kernel<<<BATCH, 192>>>(pooled, cls_lng, cls_lnb, cls_W1, cls_b1,
                               cls_W2, cls_b2, cls_W3, cls_b3, out);
}

// round 2
// speedup vs baseline: 2.1288x; 2.1288x over previous
#include <cuda_runtime.h>
#include <math.h>

#define BATCH 256
#define S 200
#define D 192
#define NH 6
#define DH 32
#define NL 3
#define FF 576
#define RD 199
#define MTOT (BATCH*S)

// ---------------- scratch (device globals) ---------------------------------
__device__ float g_h[MTOT*D];        // residual stream [B,S,D]
__device__ float g_att[MTOT*D];      // attention output / raw tokens
__device__ float g_q[MTOT*D];        // [B,H,S,Dh]
__device__ float g_k[MTOT*D];
__device__ float g_v[MTOT*D];
__device__ float g_ff[MTOT*FF];      // FFN hidden [B*S,FF]
__device__ float g_pool[BATCH*D];
__device__ float g_pooled[BATCH*D];

__device__ __forceinline__ float gelu_exact(float x) {
    return 0.5f * x * (1.0f + erff(x * 0.70710678118654752f));
}

// ============================================================================
// Kernel A: big-tile SGEMM. BM=128, BN=64, BK=16, 256 threads, 8x4 microtile.
// mode 0: A[M,192] x Wqkv[3,192,192], scatter q/k/v [B,H,S,Dh] (+bias)
// mode 1: A[M,192] x W1[192,576], GELU epilogue -> of
// mode 2: per-roi: x[b, roi*199+k] x roi_W[roi,199,192] -> raw tok (+bias)
// grid: (mtiles, ntiles, nroi)
// ============================================================================
__global__ __launch_bounds__(256) void gemmA_kernel(
    const float* __restrict__ A,
    const float* __restrict__ W,
    const float* __restrict__ bias,
    float* __restrict__ oq, float* __restrict__ ok,
    float* __restrict__ ov, float* __restrict__ of,
    int mode)
{
    __shared__ float As[16][132];
    __shared__ float Bs[16][68];

    int m0 = blockIdx.x * 128;
    int n0 = blockIdx.y * 64;
    int roi = blockIdx.z;
    int t = threadIdx.x;
    int tr = t >> 4;          // 0..15 -> 8 rows each
    int tc = t & 15;          // 0..15 -> 4 cols each
    int tr8 = tr * 8, tc4 = tc * 4;

    float acc[8][4] = {};

    const int KTOT = (mode == 2) ? RD : D;
    // B-load indices (fixed per thread)
    int bkk = t >> 4;              // 0..15
    int bc4 = (t & 15) * 4;        // 0..60

    for (int k0 = 0; k0 < KTOT; k0 += 16) {
        // ---- load A tile ----
        if (mode == 2) {
#pragma unroll
            for (int i = t; i < 2048; i += 256) {
                int r = i >> 4, c = i & 15;
                int k = k0 + c;
                As[c][r] = (k < RD)
                    ? A[(size_t)(m0 + r) * (S * RD) + (size_t)roi * RD + k]
                    : 0.f;
            }
        } else {
#pragma unroll
            for (int i = t; i < 512; i += 256) {
                int r = i >> 2, c4 = (i & 3) * 4;
                float4 a = *(const float4*)(A + (size_t)(m0 + r) * D + k0 + c4);
                As[c4 + 0][r] = a.x; As[c4 + 1][r] = a.y;
                As[c4 + 2][r] = a.z; As[c4 + 3][r] = a.w;
            }
        }
        // ---- load B tile ----
        {
            float4 bv = make_float4(0.f, 0.f, 0.f, 0.f);
            int k = k0 + bkk;
            if (mode == 0) {
                int which = n0 / D;
                int col = n0 - which * D + bc4;
                bv = *(const float4*)(W + (size_t)which * D * D + (size_t)k * D + col);
            } else if (mode == 1) {
                bv = *(const float4*)(W + (size_t)k * FF + n0 + bc4);
            } else {
                if (k < RD)
                    bv = *(const float4*)(W + (size_t)roi * RD * D + (size_t)k * D + n0 + bc4);
            }
            *(float4*)&Bs[bkk][bc4] = bv;
        }
        __syncthreads();
#pragma unroll
        for (int kk = 0; kk < 16; ++kk) {
            float4 a0 = *(const float4*)&As[kk][tr8];
            float4 a1 = *(const float4*)&As[kk][tr8 + 4];
            float4 b0 = *(const float4*)&Bs[kk][tc4];
            float a[8] = {a0.x, a0.y, a0.z, a0.w, a1.x, a1.y, a1.z, a1.w};
            float b[4] = {b0.x, b0.y, b0.z, b0.w};
#pragma unroll
            for (int i = 0; i < 8; ++i)
#pragma unroll
                for (int j = 0; j < 4; ++j) acc[i][j] += a[i] * b[j];
        }
        __syncthreads();
    }

    // ---- epilogue ----
    if (mode == 0) {
        int which = n0 / D;
        int rem0 = n0 - which * D + tc4;          // multiple of 4
        int hd = rem0 >> 5, dh0 = rem0 & 31;
        float4 bb = *(const float4*)(bias + which * D + rem0);
        float* o = (which == 0) ? oq : ((which == 1) ? ok : ov);
#pragma unroll
        for (int i = 0; i < 8; ++i) {
            int m = m0 + tr8 + i;
            int b = m / S, s = m - b * S;
            float4 v;
            v.x = acc[i][0] + bb.x; v.y = acc[i][1] + bb.y;
            v.z = acc[i][2] + bb.z; v.w = acc[i][3] + bb.w;
            *(float4*)(o + (((size_t)b * NH + hd) * S + s) * DH + dh0) = v;
        }
    } else if (mode == 1) {
        float4 bb = *(const float4*)(bias + n0 + tc4);
#pragma unroll
        for (int i = 0; i < 8; ++i) {
            int m = m0 + tr8 + i;
            float4 v;
            v.x = gelu_exact(acc[i][0] + bb.x);
            v.y = gelu_exact(acc[i][1] + bb.y);
            v.z = gelu_exact(acc[i][2] + bb.z);
            v.w = gelu_exact(acc[i][3] + bb.w);
            *(float4*)(of + (size_t)m * FF + n0 + tc4) = v;
        }
    } else {
        float4 bb = *(const float4*)(bias + (size_t)roi * D + n0 + tc4);
#pragma unroll
        for (int i = 0; i < 8; ++i) {
            int m = m0 + tr8 + i;   // batch index
            float4 v;
            v.x = acc[i][0] + bb.x; v.y = acc[i][1] + bb.y;
            v.z = acc[i][2] + bb.z; v.w = acc[i][3] + bb.w;
            *(float4*)(of + ((size_t)m * S + roi) * D + n0 + tc4) = v;
        }
    }
}

// ============================================================================
// Kernel B: [M,K] x [K,192] + bias + residual + LayerNorm, fused.
// BM=64, BN=192, BK=16, 384 threads, 8x4 microtile; C in smem for row LN.
// ============================================================================
union SmemB {
    struct { float As[16][68]; float Bs[16][196]; } g;
    float cbuf[64][192];
};

__global__ __launch_bounds__(384) void gemmB_kernel(
    const float* __restrict__ A,
    const float* __restrict__ W,
    const float* __restrict__ bias,
    const float* __restrict__ res,
    const float* __restrict__ lng,
    const float* __restrict__ lnb,
    float* __restrict__ out, int K)
{
    __shared__ SmemB sm;
    int m0 = blockIdx.x * 64;
    int t = threadIdx.x;
    int tr = t / 48;            // 0..7  -> rows tr*8..tr*8+7
    int tc = t % 48;            // 0..47 -> cols tc*4..tc*4+3
    int tr8 = tr * 8, tc4 = tc * 4;

    float acc[8][4] = {};

    for (int k0 = 0; k0 < K; k0 += 16) {
        // A tile: 64x16 = 256 float4
        for (int i = t; i < 256; i += 384) {
            int r = i >> 2, c4 = (i & 3) * 4;
            float4 a = *(const float4*)(A + (size_t)(m0 + r) * K + k0 + c4);
            sm.g.As[c4 + 0][r] = a.x; sm.g.As[c4 + 1][r] = a.y;
            sm.g.As[c4 + 2][r] = a.z; sm.g.As[c4 + 3][r] = a.w;
        }
        // B tile: 16x192 = 768 float4
#pragma unroll
        for (int i = t; i < 768; i += 384) {
            int kk = i / 48, c4 = (i % 48) * 4;
            float4 b = *(const float4*)(W + (size_t)(k0 + kk) * D + c4);
            *(float4*)&sm.g.Bs[kk][c4] = b;
        }
        __syncthreads();
#pragma unroll
        for (int kk = 0; kk < 16; ++kk) {
            float4 a0 = *(const float4*)&sm.g.As[kk][tr8];
            float4 a1 = *(const float4*)&sm.g.As[kk][tr8 + 4];
            float4 b0 = *(const float4*)&sm.g.Bs[kk][tc4];
            float a[8] = {a0.x, a0.y, a0.z, a0.w, a1.x, a1.y, a1.z, a1.w};
            float b[4] = {b0.x, b0.y, b0.z, b0.w};
#pragma unroll
            for (int i = 0; i < 8; ++i)
#pragma unroll
                for (int j = 0; j < 4; ++j) acc[i][j] += a[i] * b[j];
        }
        __syncthreads();
    }

    // write C + bias + residual into smem buffer
    float4 bb = *(const float4*)(bias + tc4);
#pragma unroll
    for (int i = 0; i < 8; ++i) {
        int m = m0 + tr8 + i;
        float4 rv = *(const float4*)(res + (size_t)m * D + tc4);
        float4 v;
        v.x = acc[i][0] + bb.x + rv.x;
        v.y = acc[i][1] + bb.y + rv.y;
        v.z = acc[i][2] + bb.z + rv.z;
        v.w = acc[i][3] + bb.w + rv.w;
        *(float4*)&sm.cbuf[tr8 + i][tc4] = v;
    }
    __syncthreads();

    // LayerNorm: warp per row
    int w = t >> 5, lane = t & 31;
    for (int r = w; r < 64; r += 12) {
        float vv[6];
        float sum = 0.f, sq = 0.f;
#pragma unroll
        for (int j = 0; j < 6; ++j) {
            vv[j] = sm.cbuf[r][lane + 32 * j];
            sum += vv[j]; sq += vv[j] * vv[j];
        }
#pragma unroll
        for (int o = 16; o > 0; o >>= 1) {
            sum += __shfl_xor_sync(0xffffffffu, sum, o);
            sq  += __shfl_xor_sync(0xffffffffu, sq,  o);
        }
        float mean = sum * (1.f / D);
        float rstd = rsqrtf(sq * (1.f / D) - mean * mean + 1e-5f);
        int m = m0 + r;
#pragma unroll
        for (int j = 0; j < 6; ++j) {
            int c = lane + 32 * j;
            out[(size_t)m * D + c] = (vv[j] - mean) * rstd * lng[c] + lnb[c];
        }
    }
}

// ============================================================================
// Kernel C: token epilogue: LN + GELU + pos_emb (warp per row)
// ============================================================================
__global__ void tok_finish_kernel(const float* __restrict__ raw,
                                  const float* __restrict__ lng,
                                  const float* __restrict__ lnb,
                                  const float* __restrict__ pos,
                                  float* __restrict__ out)
{
    int row = blockIdx.x * 8 + (threadIdx.x >> 5);
    int roi = row % S;
    int lane = threadIdx.x & 31;
    float vv[6];
    float sum = 0.f, sq = 0.f;
#pragma unroll
    for (int j = 0; j < 6; ++j) {
        vv[j] = raw[(size_t)row * D + lane + 32 * j];
        sum += vv[j]; sq += vv[j] * vv[j];
    }
#pragma unroll
    for (int o = 16; o > 0; o >>= 1) {
        sum += __shfl_xor_sync(0xffffffffu, sum, o);
        sq  += __shfl_xor_sync(0xffffffffu, sq,  o);
    }
    float mean = sum * (1.f / D);
    float rstd = rsqrtf(sq * (1.f / D) - mean * mean + 1e-5f);
#pragma unroll
    for (int j = 0; j < 6; ++j) {
        int c = lane + 32 * j;
        float v = (vv[j] - mean) * rstd * lng[(size_t)roi * D + c] + lnb[(size_t)roi * D + c];
        out[(size_t)row * D + c] = gelu_exact(v) + pos[(size_t)roi * D + c];
    }
}

// ============================================================================
// Kernel D: attention, one-pass (no max-sub; scores are O(1) for this net).
// Block per (b,h), 256 threads, thread = query; K/V staged in 100-row smem tiles.
// ============================================================================
__global__ __launch_bounds__(256) void attn_kernel(
    const float* __restrict__ q,
    const float* __restrict__ k,
    const float* __restrict__ v,
    float* __restrict__ out)
{
    __shared__ float Ks[100][DH];
    __shared__ float Vs[100][DH];
    int bh = blockIdx.x;
    int b = bh / NH, hd = bh % NH;
    size_t base = (size_t)bh * S * DH;
    int t = threadIdx.x;

    float qv[DH];
    if (t < S) {
#pragma unroll
        for (int c4 = 0; c4 < DH; c4 += 4) {
            float4 x = *(const float4*)(q + base + (size_t)t * DH + c4);
            qv[c4+0] = x.x * 0.17677669529663687f;
            qv[c4+1] = x.y * 0.17677669529663687f;
            qv[c4+2] = x.z * 0.17677669529663687f;
            qv[c4+3] = x.w * 0.17677669529663687f;
        }
    }

    float l = 0.f;
    float o[DH] = {};

#pragma unroll
    for (int tile = 0; tile < 2; ++tile) {
        int s0 = tile * 100;
        __syncthreads();
        for (int i = t; i < 800; i += 256) {
            int r = i >> 3, c4 = (i & 7) * 4;
            *(float4*)&Ks[r][c4] = *(const float4*)(k + base + (size_t)(s0 + r) * DH + c4);
            *(float4*)&Vs[r][c4] = *(const float4*)(v + base + (size_t)(s0 + r) * DH + c4);
        }
        __syncthreads();
        if (t < S) {
            for (int s = 0; s < 100; ++s) {
                float sc = 0.f;
#pragma unroll
                for (int c4 = 0; c4 < DH; c4 += 4) {
                    float4 kk = *(const float4*)&Ks[s][c4];
                    sc += qv[c4+0] * kk.x + qv[c4+1] * kk.y
                        + qv[c4+2] * kk.z + qv[c4+3] * kk.w;
                }
                float e = __expf(sc);
                l += e;
#pragma unroll
                for (int c4 = 0; c4 < DH; c4 += 4) {
                    float4 vv = *(const float4*)&Vs[s][c4];
                    o[c4+0] += e * vv.x; o[c4+1] += e * vv.y;
                    o[c4+2] += e * vv.z; o[c4+3] += e * vv.w;
                }
            }
        }
    }

    if (t < S) {
        float inv = 1.f / l;
        float* op = out + ((size_t)b * S + t) * D + hd * DH;
#pragma unroll
        for (int c4 = 0; c4 < DH; c4 += 4) {
            float4 vv;
            vv.x = o[c4+0] * inv; vv.y = o[c4+1] * inv;
            vv.z = o[c4+2] * inv; vv.w = o[c4+3] * inv;
            *(float4*)(op + c4) = vv;
        }
    }
}

// ---------------- kernel 5: pooled attention (Q=1 via linearity) -----------
__global__ void pool_attn_kernel(const float* __restrict__ q,
                                 const float* __restrict__ k,
                                 const float* __restrict__ v,
                                 float* __restrict__ out)
{
    __shared__ float qm[DH];
    __shared__ float sc[S];
    __shared__ float red[2];
    int bh = blockIdx.x;
    int b = bh / NH, hd = bh % NH;
    size_t base = (size_t)bh * S * DH;
    int t = threadIdx.x;
    if (t < DH) {
        float s = 0.f;
        for (int j = 0; j < S; ++j) s += q[base + j * DH + t];
        qm[t] = s * (1.f / S) * 0.17677669529663687f;
    }
    __syncthreads();
    if (t < S) {
        float x = 0.f;
#pragma unroll
        for (int i = 0; i < DH; ++i) x += qm[i] * k[base + t * DH + i];
        sc[t] = x;
    }
    __syncthreads();
    if (t == 0) {
        float mx = -1e30f;
        for (int s = 0; s < S; ++s) mx = fmaxf(mx, sc[s]);
        red[0] = mx;
    }
    __syncthreads();
    if (t < S) sc[t] = __expf(sc[t] - red[0]);
    __syncthreads();
    if (t == 0) {
        float l = 0.f;
        for (int s = 0; s < S; ++s) l += sc[s];
        red[1] = 1.f / l;
    }
    __syncthreads();
    if (t < DH) {
        float o = 0.f;
        for (int s = 0; s < S; ++s) o += sc[s] * v[base + s * DH + t];
        out[(size_t)b * D + hd * DH + t] = o * red[1];
    }
}

// ---------------- kernel 6: pooled projection ------------------------------
__global__ void pool_proj_kernel(const float* __restrict__ in,
                                 const float* __restrict__ W,
                                 const float* __restrict__ bias,
                                 float* __restrict__ out)
{
    __shared__ float row[D];
    int b = blockIdx.x, d = threadIdx.x;
    row[d] = in[(size_t)b * D + d];
    __syncthreads();
    float s = bias[d];
    for (int k = 0; k < D; ++k) s += row[k] * W[(size_t)k * D + d];
    out[(size_t)b * D + d] = s;
}

// ---------------- kernel 7: classifier head --------------------------------
__global__ void cls_kernel(const float* __restrict__ in,
                           const float* __restrict__ g,  const float* __restrict__ bt,
                           const float* __restrict__ W1, const float* __restrict__ b1,
                           const float* __restrict__ W2, const float* __restrict__ b2,
                           const float* __restrict__ W3, const float* __restrict__ b3,
                           float* __restrict__ out)
{
    __shared__ float z[D];
    __shared__ float z1[96];
    __shared__ float z2[48];
    __shared__ float red[2];
    int b = blockIdx.x, t = threadIdx.x;
    float v = in[(size_t)b * D + t];
    z[t] = v;
    __syncthreads();
    if (t == 0) {
        float s = 0.f, sq = 0.f;
        for (int i = 0; i < D; ++i) { s += z[i]; sq += z[i] * z[i]; }
        float m = s / D;
        red[0] = m;
        red[1] = rsqrtf(sq / D - m * m + 1e-5f);
    }
    __syncthreads();
    z[t] = (v - red[0]) * red[1] * g[t] + bt[t];
    __syncthreads();
    if (t < 96) {
        float a = b1[t];
        for (int k = 0; k < D; ++k) a += z[k] * W1[k * 96 + t];
        z1[t] = gelu_exact(a);
    }
    __syncthreads();
    if (t < 48) {
        float a = b2[t];
        for (int k = 0; k < 96; ++k) a += z1[k] * W2[k * 48 + t];
        z2[t] = gelu_exact(a);
    }
    __syncthreads();
    if (t < 2) {
        float a = b3[t];
        for (int k = 0; k < 48; ++k) a += z2[k] * W3[k * 2 + t];
        out[(size_t)b * 2 + t] = a;
    }
}

// ---------------- launch ----------------------------------------------------
extern "C" void kernel_launch(void* const* d_in, const int* in_sizes, int n_in,
                              void* d_out, int out_size)
{
    const float* x        = (const float*)d_in[0];
    const float* roi_W    = (const float*)d_in[1];
    const float* roi_b    = (const float*)d_in[2];
    const float* roi_lng  = (const float*)d_in[3];
    const float* roi_lnb  = (const float*)d_in[4];
    const float* pos_emb  = (const float*)d_in[5];
    const float* enc_Wqkv = (const float*)d_in[6];
    const float* enc_bqkv = (const float*)d_in[7];
    const float* enc_Wo   = (const float*)d_in[8];
    const float* enc_bo   = (const float*)d_in[9];
    const float* enc_ln1g = (const float*)d_in[10];
    const float* enc_ln1b = (const float*)d_in[11];
    const float* enc_W1   = (const float*)d_in[12];
    const float* enc_b1   = (const float*)d_in[13];
    const float* enc_W2   = (const float*)d_in[14];
    const float* enc_b2   = (const float*)d_in[15];
    const float* enc_ln2g = (const float*)d_in[16];
    const float* enc_ln2b = (const float*)d_in[17];
    const float* pool_Wqkv= (const float*)d_in[18];
    const float* pool_bqkv= (const float*)d_in[19];
    const float* pool_Wo  = (const float*)d_in[20];
    const float* pool_bo  = (const float*)d_in[21];
    const float* cls_lng  = (const float*)d_in[22];
    const float* cls_lnb  = (const float*)d_in[23];
    const float* cls_W1   = (const float*)d_in[24];
    const float* cls_b1   = (const float*)d_in[25];
    const float* cls_W2   = (const float*)d_in[26];
    const float* cls_b2   = (const float*)d_in[27];
    const float* cls_W3   = (const float*)d_in[28];
    const float* cls_b3   = (const float*)d_in[29];
    float* out = (float*)d_out;

    float *h, *att, *q, *k, *v, *ff, *pool, *pooled;
    cudaGetSymbolAddress((void**)&h,      g_h);
    cudaGetSymbolAddress((void**)&att,    g_att);
    cudaGetSymbolAddress((void**)&q,      g_q);
    cudaGetSymbolAddress((void**)&k,      g_k);
    cudaGetSymbolAddress((void**)&v,      g_v);
    cudaGetSymbolAddress((void**)&ff,     g_ff);
    cudaGetSymbolAddress((void**)&pool,   g_pool);
    cudaGetSymbolAddress((void**)&pooled, g_pooled);

    // tokenizer: per-roi GEMM (raw into att), then LN+GELU+pos
    gemmA_kernel<<<dim3(2, 3, 200), 256>>>(x, roi_W, roi_b,
                                           nullptr, nullptr, nullptr, att, 2);
    tok_finish_kernel<<<MTOT / 8, 256>>>(att, roi_lng, roi_lnb, pos_emb, h);

    // encoder layers
    for (int l = 0; l < NL; ++l) {
        gemmA_kernel<<<dim3(MTOT / 128, 9, 1), 256>>>(h,
            enc_Wqkv + (size_t)l * 3 * D * D, enc_bqkv + (size_t)l * 3 * D,
            q, k, v, nullptr, 0);
        attn_kernel<<<BATCH * NH, 256>>>(q, k, v, att);
        gemmB_kernel<<<MTOT / 64, 384>>>(att, enc_Wo + (size_t)l * D * D,
                                         enc_bo + l * D, h,
                                         enc_ln1g + l * D, enc_ln1b + l * D, h, D);
        gemmA_kernel<<<dim3(MTOT / 128, 9, 1), 256>>>(h,
            enc_W1 + (size_t)l * D * FF, enc_b1 + l * FF,
            nullptr, nullptr, nullptr, ff, 1);
        gemmB_kernel<<<MTOT / 64, 384>>>(ff, enc_W2 + (size_t)l * FF * D,
                                         enc_b2 + l * D, h,
                                         enc_ln2g + l * D, enc_ln2b + l * D, h, FF);
    }

    // pooling
    gemmA_kernel<<<dim3(MTOT / 128, 9, 1), 256>>>(h, pool_Wqkv, pool_bqkv,
                                                  q, k, v, nullptr, 0);
    pool_attn_kernel<<<BATCH * NH, 256>>>(q, k, v, pool);
    pool_proj_kernel<<<BATCH, 192>>>(pool, pool_Wo, pool_bo, pooled);

    // classifier
    cls_kernel<<<BATCH, 192>>>(pooled, cls_lng, cls_lnb, cls_W1, cls_b1,
                               cls_W2, cls_b2, cls_W3, cls_b3, out);
}

// round 3
// speedup vs baseline: 2.3367x; 1.0977x over previous
#include <cuda_runtime.h>
#include <math.h>

#define BATCH 256
#define S 200
#define D 192
#define NH 6
#define DH 32
#define NL 3
#define FF 576
#define RD 199
#define MTOT (BATCH*S)

typedef unsigned long long ull;

// ---------------- f32x2 packed-FMA helpers ---------------------------------
__device__ __forceinline__ ull pack2(float x, float y) {
    ull r; asm("mov.b64 %0, {%1, %2};" : "=l"(r) : "f"(x), "f"(y)); return r;
}
__device__ __forceinline__ ull bcast2(float x) {
    ull r; asm("mov.b64 %0, {%1, %1};" : "=l"(r) : "f"(x)); return r;
}
__device__ __forceinline__ void fma2(ull& d, ull a, ull b) {
    asm("fma.rn.f32x2 %0, %1, %2, %0;" : "+l"(d) : "l"(a), "l"(b));
}
__device__ __forceinline__ float2 unpk(ull v) {
    float2 f; asm("mov.b64 {%0, %1}, %2;" : "=f"(f.x), "=f"(f.y) : "l"(v)); return f;
}

// ---------------- scratch (device globals) ---------------------------------
__device__ float g_h[MTOT*D];
__device__ float g_att[MTOT*D];
__device__ float g_q[MTOT*D];
__device__ float g_k[MTOT*D];
__device__ float g_v[MTOT*D];
__device__ float g_ff[MTOT*FF];
__device__ float g_pool[BATCH*D];
__device__ float g_pooled[BATCH*D];

__device__ __forceinline__ float gelu_exact(float x) {
    return 0.5f * x * (1.0f + erff(x * 0.70710678118654752f));
}

// ============================================================================
// Kernel A: big-tile SGEMM with FFMA2. BM=128, BN=64, BK=16, 256 thr.
// microtile 8x4 = 4 row-pairs x 4 cols, packed accumulators.
// mode 0: A[M,192] x Wqkv[3,192,192] -> scatter q/k/v
// mode 1: A[M,192] x W1[192,576] -> GELU -> of
// mode 2: per-roi tokenizer GEMM
// ============================================================================
__global__ __launch_bounds__(256) void gemmA_kernel(
    const float* __restrict__ A,
    const float* __restrict__ W,
    const float* __restrict__ bias,
    float* __restrict__ oq, float* __restrict__ ok,
    float* __restrict__ ov, float* __restrict__ of,
    int mode)
{
    __shared__ float As[16][132];
    __shared__ float Bs[16][68];

    int m0 = blockIdx.x * 128;
    int n0 = blockIdx.y * 64;
    int roi = blockIdx.z;
    int t = threadIdx.x;
    int tr8 = (t >> 4) * 8;
    int tc4 = (t & 15) * 4;

    ull acc[4][4] = {};   // [row-pair][col], zero bits == (0.f,0.f)

    const int KTOT = (mode == 2) ? RD : D;
    int bkk = t >> 4;
    int bc4 = (t & 15) * 4;

    for (int k0 = 0; k0 < KTOT; k0 += 16) {
        if (mode == 2) {
#pragma unroll
            for (int i = t; i < 2048; i += 256) {
                int r = i >> 4, c = i & 15;
                int k = k0 + c;
                As[c][r] = (k < RD)
                    ? A[(size_t)(m0 + r) * (S * RD) + (size_t)roi * RD + k]
                    : 0.f;
            }
        } else {
#pragma unroll
            for (int i = t; i < 512; i += 256) {
                int r = i >> 2, c4 = (i & 3) * 4;
                float4 a = *(const float4*)(A + (size_t)(m0 + r) * D + k0 + c4);
                As[c4 + 0][r] = a.x; As[c4 + 1][r] = a.y;
                As[c4 + 2][r] = a.z; As[c4 + 3][r] = a.w;
            }
        }
        {
            float4 bv = make_float4(0.f, 0.f, 0.f, 0.f);
            int k = k0 + bkk;
            if (mode == 0) {
                int which = n0 / D;
                int col = n0 - which * D + bc4;
                bv = *(const float4*)(W + (size_t)which * D * D + (size_t)k * D + col);
            } else if (mode == 1) {
                bv = *(const float4*)(W + (size_t)k * FF + n0 + bc4);
            } else {
                if (k < RD)
                    bv = *(const float4*)(W + (size_t)roi * RD * D + (size_t)k * D + n0 + bc4);
            }
            *(float4*)&Bs[bkk][bc4] = bv;
        }
        __syncthreads();
#pragma unroll
        for (int kk = 0; kk < 16; ++kk) {
            ulonglong2 a0 = *(const ulonglong2*)&As[kk][tr8];
            ulonglong2 a1 = *(const ulonglong2*)&As[kk][tr8 + 4];
            float4 b = *(const float4*)&Bs[kk][tc4];
            ull b0 = bcast2(b.x), b1 = bcast2(b.y), b2 = bcast2(b.z), b3 = bcast2(b.w);
            ull ap[4] = {a0.x, a0.y, a1.x, a1.y};
#pragma unroll
            for (int i = 0; i < 4; ++i) {
                fma2(acc[i][0], ap[i], b0);
                fma2(acc[i][1], ap[i], b1);
                fma2(acc[i][2], ap[i], b2);
                fma2(acc[i][3], ap[i], b3);
            }
        }
        __syncthreads();
    }

    // ---- epilogue ----
    if (mode == 0) {
        int which = n0 / D;
        int rem0 = n0 - which * D + tc4;
        int hd = rem0 >> 5, dh0 = rem0 & 31;
        float4 bb = *(const float4*)(bias + which * D + rem0);
        float* o = (which == 0) ? oq : ((which == 1) ? ok : ov);
#pragma unroll
        for (int i = 0; i < 4; ++i) {
            float2 u0 = unpk(acc[i][0]), u1 = unpk(acc[i][1]);
            float2 u2 = unpk(acc[i][2]), u3 = unpk(acc[i][3]);
            int m = m0 + tr8 + i * 2;
            int b = m / S, s = m - b * S;
            float4 v0 = make_float4(u0.x + bb.x, u1.x + bb.y, u2.x + bb.z, u3.x + bb.w);
            *(float4*)(o + (((size_t)b * NH + hd) * S + s) * DH + dh0) = v0;
            m++; b = m / S; s = m - b * S;
            float4 v1 = make_float4(u0.y + bb.x, u1.y + bb.y, u2.y + bb.z, u3.y + bb.w);
            *(float4*)(o + (((size_t)b * NH + hd) * S + s) * DH + dh0) = v1;
        }
    } else if (mode == 1) {
        float4 bb = *(const float4*)(bias + n0 + tc4);
#pragma unroll
        for (int i = 0; i < 4; ++i) {
            float2 u0 = unpk(acc[i][0]), u1 = unpk(acc[i][1]);
            float2 u2 = unpk(acc[i][2]), u3 = unpk(acc[i][3]);
            int m = m0 + tr8 + i * 2;
            float4 v0 = make_float4(gelu_exact(u0.x + bb.x), gelu_exact(u1.x + bb.y),
                                    gelu_exact(u2.x + bb.z), gelu_exact(u3.x + bb.w));
            *(float4*)(of + (size_t)m * FF + n0 + tc4) = v0;
            float4 v1 = make_float4(gelu_exact(u0.y + bb.x), gelu_exact(u1.y + bb.y),
                                    gelu_exact(u2.y + bb.z), gelu_exact(u3.y + bb.w));
            *(float4*)(of + (size_t)(m + 1) * FF + n0 + tc4) = v1;
        }
    } else {
        float4 bb = *(const float4*)(bias + (size_t)roi * D + n0 + tc4);
#pragma unroll
        for (int i = 0; i < 4; ++i) {
            float2 u0 = unpk(acc[i][0]), u1 = unpk(acc[i][1]);
            float2 u2 = unpk(acc[i][2]), u3 = unpk(acc[i][3]);
            int m = m0 + tr8 + i * 2;
            float4 v0 = make_float4(u0.x + bb.x, u1.x + bb.y, u2.x + bb.z, u3.x + bb.w);
            *(float4*)(of + ((size_t)m * S + roi) * D + n0 + tc4) = v0;
            float4 v1 = make_float4(u0.y + bb.x, u1.y + bb.y, u2.y + bb.z, u3.y + bb.w);
            *(float4*)(of + ((size_t)(m + 1) * S + roi) * D + n0 + tc4) = v1;
        }
    }
}

// ============================================================================
// Kernel B: [M,K] x [K,192] + bias + residual + LN, FFMA2 inner loop.
// BM=64, BN=192, BK=16, 384 threads.
// ============================================================================
union SmemB {
    struct { float As[16][68]; float Bs[16][196]; } g;
    float cbuf[64][192];
};

__global__ __launch_bounds__(384) void gemmB_kernel(
    const float* __restrict__ A,
    const float* __restrict__ W,
    const float* __restrict__ bias,
    const float* __restrict__ res,
    const float* __restrict__ lng,
    const float* __restrict__ lnb,
    float* __restrict__ out, int K)
{
    __shared__ SmemB sm;
    int m0 = blockIdx.x * 64;
    int t = threadIdx.x;
    int tr8 = (t / 48) * 8;
    int tc4 = (t % 48) * 4;

    ull acc[4][4] = {};

    for (int k0 = 0; k0 < K; k0 += 16) {
        for (int i = t; i < 256; i += 384) {
            int r = i >> 2, c4 = (i & 3) * 4;
            float4 a = *(const float4*)(A + (size_t)(m0 + r) * K + k0 + c4);
            sm.g.As[c4 + 0][r] = a.x; sm.g.As[c4 + 1][r] = a.y;
            sm.g.As[c4 + 2][r] = a.z; sm.g.As[c4 + 3][r] = a.w;
        }
#pragma unroll
        for (int i = t; i < 768; i += 384) {
            int kk = i / 48, c4 = (i % 48) * 4;
            *(float4*)&sm.g.Bs[kk][c4] = *(const float4*)(W + (size_t)(k0 + kk) * D + c4);
        }
        __syncthreads();
#pragma unroll
        for (int kk = 0; kk < 16; ++kk) {
            ulonglong2 a0 = *(const ulonglong2*)&sm.g.As[kk][tr8];
            ulonglong2 a1 = *(const ulonglong2*)&sm.g.As[kk][tr8 + 4];
            float4 b = *(const float4*)&sm.g.Bs[kk][tc4];
            ull b0 = bcast2(b.x), b1 = bcast2(b.y), b2 = bcast2(b.z), b3 = bcast2(b.w);
            ull ap[4] = {a0.x, a0.y, a1.x, a1.y};
#pragma unroll
            for (int i = 0; i < 4; ++i) {
                fma2(acc[i][0], ap[i], b0);
                fma2(acc[i][1], ap[i], b1);
                fma2(acc[i][2], ap[i], b2);
                fma2(acc[i][3], ap[i], b3);
            }
        }
        __syncthreads();
    }

    float4 bb = *(const float4*)(bias + tc4);
#pragma unroll
    for (int i = 0; i < 4; ++i) {
        float2 u0 = unpk(acc[i][0]), u1 = unpk(acc[i][1]);
        float2 u2 = unpk(acc[i][2]), u3 = unpk(acc[i][3]);
        int r = tr8 + i * 2;
        int m = m0 + r;
        float4 rv0 = *(const float4*)(res + (size_t)m * D + tc4);
        float4 v0 = make_float4(u0.x + bb.x + rv0.x, u1.x + bb.y + rv0.y,
                                u2.x + bb.z + rv0.z, u3.x + bb.w + rv0.w);
        *(float4*)&sm.cbuf[r][tc4] = v0;
        float4 rv1 = *(const float4*)(res + (size_t)(m + 1) * D + tc4);
        float4 v1 = make_float4(u0.y + bb.x + rv1.x, u1.y + bb.y + rv1.y,
                                u2.y + bb.z + rv1.z, u3.y + bb.w + rv1.w);
        *(float4*)&sm.cbuf[r + 1][tc4] = v1;
    }
    __syncthreads();

    int w = t >> 5, lane = t & 31;
    for (int r = w; r < 64; r += 12) {
        float vv[6];
        float sum = 0.f, sq = 0.f;
#pragma unroll
        for (int j = 0; j < 6; ++j) {
            vv[j] = sm.cbuf[r][lane + 32 * j];
            sum += vv[j]; sq += vv[j] * vv[j];
        }
#pragma unroll
        for (int o = 16; o > 0; o >>= 1) {
            sum += __shfl_xor_sync(0xffffffffu, sum, o);
            sq  += __shfl_xor_sync(0xffffffffu, sq,  o);
        }
        float mean = sum * (1.f / D);
        float rstd = rsqrtf(sq * (1.f / D) - mean * mean + 1e-5f);
        int m = m0 + r;
#pragma unroll
        for (int j = 0; j < 6; ++j) {
            int c = lane + 32 * j;
            out[(size_t)m * D + c] = (vv[j] - mean) * rstd * lng[c] + lnb[c];
        }
    }
}

// ============================================================================
// Kernel C: token epilogue: LN + GELU + pos_emb (warp per row)
// ============================================================================
__global__ void tok_finish_kernel(const float* __restrict__ raw,
                                  const float* __restrict__ lng,
                                  const float* __restrict__ lnb,
                                  const float* __restrict__ pos,
                                  float* __restrict__ out)
{
    int row = blockIdx.x * 8 + (threadIdx.x >> 5);
    int roi = row % S;
    int lane = threadIdx.x & 31;
    float vv[6];
    float sum = 0.f, sq = 0.f;
#pragma unroll
    for (int j = 0; j < 6; ++j) {
        vv[j] = raw[(size_t)row * D + lane + 32 * j];
        sum += vv[j]; sq += vv[j] * vv[j];
    }
#pragma unroll
    for (int o = 16; o > 0; o >>= 1) {
        sum += __shfl_xor_sync(0xffffffffu, sum, o);
        sq  += __shfl_xor_sync(0xffffffffu, sq,  o);
    }
    float mean = sum * (1.f / D);
    float rstd = rsqrtf(sq * (1.f / D) - mean * mean + 1e-5f);
#pragma unroll
    for (int j = 0; j < 6; ++j) {
        int c = lane + 32 * j;
        float v = (vv[j] - mean) * rstd * lng[(size_t)roi * D + c] + lnb[(size_t)roi * D + c];
        out[(size_t)row * D + c] = gelu_exact(v) + pos[(size_t)roi * D + c];
    }
}

// ============================================================================
// Kernel D: attention, FFMA2 inner loops, one-pass softmax (scores O(1)).
// ============================================================================
__global__ __launch_bounds__(256) void attn_kernel(
    const float* __restrict__ q,
    const float* __restrict__ k,
    const float* __restrict__ v,
    float* __restrict__ out)
{
    __shared__ float Ks[100][DH];
    __shared__ float Vs[100][DH];
    int bh = blockIdx.x;
    int b = bh / NH, hd = bh % NH;
    size_t base = (size_t)bh * S * DH;
    int t = threadIdx.x;

    ull qp2[16];
    if (t < S) {
#pragma unroll
        for (int c4 = 0; c4 < DH; c4 += 4) {
            float4 x = *(const float4*)(q + base + (size_t)t * DH + c4);
            qp2[(c4 >> 1) + 0] = pack2(x.x * 0.17677669529663687f, x.y * 0.17677669529663687f);
            qp2[(c4 >> 1) + 1] = pack2(x.z * 0.17677669529663687f, x.w * 0.17677669529663687f);
        }
    }

    float l = 0.f;
    ull o2[16] = {};

#pragma unroll
    for (int tile = 0; tile < 2; ++tile) {
        int s0 = tile * 100;
        __syncthreads();
        for (int i = t; i < 800; i += 256) {
            int r = i >> 3, c4 = (i & 7) * 4;
            *(float4*)&Ks[r][c4] = *(const float4*)(k + base + (size_t)(s0 + r) * DH + c4);
            *(float4*)&Vs[r][c4] = *(const float4*)(v + base + (size_t)(s0 + r) * DH + c4);
        }
        __syncthreads();
        if (t < S) {
            for (int s = 0; s < 100; ++s) {
                ull sc2 = 0;
#pragma unroll
                for (int c4 = 0; c4 < DH; c4 += 4) {
                    ulonglong2 kk = *(const ulonglong2*)&Ks[s][c4];
                    fma2(sc2, qp2[(c4 >> 1) + 0], kk.x);
                    fma2(sc2, qp2[(c4 >> 1) + 1], kk.y);
                }
                float2 sp = unpk(sc2);
                float e = __expf(sp.x + sp.y);
                l += e;
                ull eb = bcast2(e);
#pragma unroll
                for (int c4 = 0; c4 < DH; c4 += 4) {
                    ulonglong2 vv = *(const ulonglong2*)&Vs[s][c4];
                    fma2(o2[(c4 >> 1) + 0], eb, vv.x);
                    fma2(o2[(c4 >> 1) + 1], eb, vv.y);
                }
            }
        }
    }

    if (t < S) {
        float inv = 1.f / l;
        float* op = out + ((size_t)b * S + t) * D + hd * DH;
#pragma unroll
        for (int c4 = 0; c4 < DH; c4 += 4) {
            float2 u0 = unpk(o2[(c4 >> 1) + 0]);
            float2 u1 = unpk(o2[(c4 >> 1) + 1]);
            float4 vv = make_float4(u0.x * inv, u0.y * inv, u1.x * inv, u1.y * inv);
            *(float4*)(op + c4) = vv;
        }
    }
}

// ---------------- pooled attention (Q=1 via linearity) ---------------------
__global__ void pool_attn_kernel(const float* __restrict__ q,
                                 const float* __restrict__ k,
                                 const float* __restrict__ v,
                                 float* __restrict__ out)
{
    __shared__ float qm[DH];
    __shared__ float sc[S];
    __shared__ float red[2];
    int bh = blockIdx.x;
    int b = bh / NH, hd = bh % NH;
    size_t base = (size_t)bh * S * DH;
    int t = threadIdx.x;
    if (t < DH) {
        float s = 0.f;
        for (int j = 0; j < S; ++j) s += q[base + j * DH + t];
        qm[t] = s * (1.f / S) * 0.17677669529663687f;
    }
    __syncthreads();
    if (t < S) {
        float x = 0.f;
#pragma unroll
        for (int i = 0; i < DH; ++i) x += qm[i] * k[base + t * DH + i];
        sc[t] = x;
    }
    __syncthreads();
    if (t == 0) {
        float mx = -1e30f;
        for (int s = 0; s < S; ++s) mx = fmaxf(mx, sc[s]);
        red[0] = mx;
    }
    __syncthreads();
    if (t < S) sc[t] = __expf(sc[t] - red[0]);
    __syncthreads();
    if (t == 0) {
        float l = 0.f;
        for (int s = 0; s < S; ++s) l += sc[s];
        red[1] = 1.f / l;
    }
    __syncthreads();
    if (t < DH) {
        float o = 0.f;
        for (int s = 0; s < S; ++s) o += sc[s] * v[base + s * DH + t];
        out[(size_t)b * D + hd * DH + t] = o * red[1];
    }
}

// ---------------- pooled projection ----------------------------------------
__global__ void pool_proj_kernel(const float* __restrict__ in,
                                 const float* __restrict__ W,
                                 const float* __restrict__ bias,
                                 float* __restrict__ out)
{
    __shared__ float row[D];
    int b = blockIdx.x, d = threadIdx.x;
    row[d] = in[(size_t)b * D + d];
    __syncthreads();
    float s = bias[d];
    for (int k = 0; k < D; ++k) s += row[k] * W[(size_t)k * D + d];
    out[(size_t)b * D + d] = s;
}

// ---------------- classifier head ------------------------------------------
__global__ void cls_kernel(const float* __restrict__ in,
                           const float* __restrict__ g,  const float* __restrict__ bt,
                           const float* __restrict__ W1, const float* __restrict__ b1,
                           const float* __restrict__ W2, const float* __restrict__ b2,
                           const float* __restrict__ W3, const float* __restrict__ b3,
                           float* __restrict__ out)
{
    __shared__ float z[D];
    __shared__ float z1[96];
    __shared__ float z2[48];
    __shared__ float red[2];
    int b = blockIdx.x, t = threadIdx.x;
    float v = in[(size_t)b * D + t];
    z[t] = v;
    __syncthreads();
    if (t == 0) {
        float s = 0.f, sq = 0.f;
        for (int i = 0; i < D; ++i) { s += z[i]; sq += z[i] * z[i]; }
        float m = s / D;
        red[0] = m;
        red[1] = rsqrtf(sq / D - m * m + 1e-5f);
    }
    __syncthreads();
    z[t] = (v - red[0]) * red[1] * g[t] + bt[t];
    __syncthreads();
    if (t < 96) {
        float a = b1[t];
        for (int k = 0; k < D; ++k) a += z[k] * W1[k * 96 + t];
        z1[t] = gelu_exact(a);
    }
    __syncthreads();
    if (t < 48) {
        float a = b2[t];
        for (int k = 0; k < 96; ++k) a += z1[k] * W2[k * 48 + t];
        z2[t] = gelu_exact(a);
    }
    __syncthreads();
    if (t < 2) {
        float a = b3[t];
        for (int k = 0; k < 48; ++k) a += z2[k] * W3[k * 2 + t];
        out[(size_t)b * 2 + t] = a;
    }
}

// ---------------- launch ----------------------------------------------------
extern "C" void kernel_launch(void* const* d_in, const int* in_sizes, int n_in,
                              void* d_out, int out_size)
{
    const float* x        = (const float*)d_in[0];
    const float* roi_W    = (const float*)d_in[1];
    const float* roi_b    = (const float*)d_in[2];
    const float* roi_lng  = (const float*)d_in[3];
    const float* roi_lnb  = (const float*)d_in[4];
    const float* pos_emb  = (const float*)d_in[5];
    const float* enc_Wqkv = (const float*)d_in[6];
    const float* enc_bqkv = (const float*)d_in[7];
    const float* enc_Wo   = (const float*)d_in[8];
    const float* enc_bo   = (const float*)d_in[9];
    const float* enc_ln1g = (const float*)d_in[10];
    const float* enc_ln1b = (const float*)d_in[11];
    const float* enc_W1   = (const float*)d_in[12];
    const float* enc_b1   = (const float*)d_in[13];
    const float* enc_W2   = (const float*)d_in[14];
    const float* enc_b2   = (const float*)d_in[15];
    const float* enc_ln2g = (const float*)d_in[16];
    const float* enc_ln2b = (const float*)d_in[17];
    const float* pool_Wqkv= (const float*)d_in[18];
    const float* pool_bqkv= (const float*)d_in[19];
    const float* pool_Wo  = (const float*)d_in[20];
    const float* pool_bo  = (const float*)d_in[21];
    const float* cls_lng  = (const float*)d_in[22];
    const float* cls_lnb  = (const float*)d_in[23];
    const float* cls_W1   = (const float*)d_in[24];
    const float* cls_b1   = (const float*)d_in[25];
    const float* cls_W2   = (const float*)d_in[26];
    const float* cls_b2   = (const float*)d_in[27];
    const float* cls_W3   = (const float*)d_in[28];
    const float* cls_b3   = (const float*)d_in[29];
    float* out = (float*)d_out;

    float *h, *att, *q, *k, *v, *ff, *pool, *pooled;
    cudaGetSymbolAddress((void**)&h,      g_h);
    cudaGetSymbolAddress((void**)&att,    g_att);
    cudaGetSymbolAddress((void**)&q,      g_q);
    cudaGetSymbolAddress((void**)&k,      g_k);
    cudaGetSymbolAddress((void**)&v,      g_v);
    cudaGetSymbolAddress((void**)&ff,     g_ff);
    cudaGetSymbolAddress((void**)&pool,   g_pool);
    cudaGetSymbolAddress((void**)&pooled, g_pooled);

    gemmA_kernel<<<dim3(2, 3, 200), 256>>>(x, roi_W, roi_b,
                                           nullptr, nullptr, nullptr, att, 2);
    tok_finish_kernel<<<MTOT / 8, 256>>>(att, roi_lng, roi_lnb, pos_emb, h);

    for (int l = 0; l < NL; ++l) {
        gemmA_kernel<<<dim3(MTOT / 128, 9, 1), 256>>>(h,
            enc_Wqkv + (size_t)l * 3 * D * D, enc_bqkv + (size_t)l * 3 * D,
            q, k, v, nullptr, 0);
        attn_kernel<<<BATCH * NH, 256>>>(q, k, v, att);
        gemmB_kernel<<<MTOT / 64, 384>>>(att, enc_Wo + (size_t)l * D * D,
                                         enc_bo + l * D, h,
                                         enc_ln1g + l * D, enc_ln1b + l * D, h, D);
        gemmA_kernel<<<dim3(MTOT / 128, 9, 1), 256>>>(h,
            enc_W1 + (size_t)l * D * FF, enc_b1 + l * FF,
            nullptr, nullptr, nullptr, ff, 1);
        gemmB_kernel<<<MTOT / 64, 384>>>(ff, enc_W2 + (size_t)l * FF * D,
                                         enc_b2 + l * D, h,
                                         enc_ln2g + l * D, enc_ln2b + l * D, h, FF);
    }

    gemmA_kernel<<<dim3(MTOT / 128, 9, 1), 256>>>(h, pool_Wqkv, pool_bqkv,
                                                  q, k, v, nullptr, 0);
    pool_attn_kernel<<<BATCH * NH, 256>>>(q, k, v, pool);
    pool_proj_kernel<<<BATCH, 192>>>(pool, pool_Wo, pool_bo, pooled);

    cls_kernel<<<BATCH, 192>>>(pooled, cls_lng, cls_lnb, cls_W1, cls_b1,
                               cls_W2, cls_b2, cls_W3, cls_b3, out);
}

// round 4
// speedup vs baseline: 2.4167x; 1.0342x over previous
#include <cuda_runtime.h>
#include <cuda_bf16.h>
#include <math.h>

#define BATCH 256
#define S 200
#define D 192
#define NH 6
#define DH 32
#define NL 3
#define FF 576
#define RD 199
#define MTOT (BATCH*S)

typedef unsigned long long ull;

// ---------------- f32x2 packed-FMA helpers (attention) ---------------------
__device__ __forceinline__ ull pack2(float x, float y) {
    ull r; asm("mov.b64 %0, {%1, %2};" : "=l"(r) : "f"(x), "f"(y)); return r;
}
__device__ __forceinline__ ull bcast2(float x) {
    ull r; asm("mov.b64 %0, {%1, %1};" : "=l"(r) : "f"(x)); return r;
}
__device__ __forceinline__ void fma2(ull& d, ull a, ull b) {
    asm("fma.rn.f32x2 %0, %1, %2, %0;" : "+l"(d) : "l"(a), "l"(b));
}
__device__ __forceinline__ float2 unpk(ull v) {
    float2 f; asm("mov.b64 {%0, %1}, %2;" : "=f"(f.x), "=f"(f.y) : "l"(v)); return f;
}

// ---------------- mma helpers -----------------------------------------------
__device__ __forceinline__ unsigned smem_u32(const void* p) {
    return (unsigned)__cvta_generic_to_shared(p);
}
__device__ __forceinline__ void ldsm_x4(unsigned addr, unsigned& r0, unsigned& r1,
                                        unsigned& r2, unsigned& r3) {
    asm volatile("ldmatrix.sync.aligned.m8n8.x4.shared.b16 {%0,%1,%2,%3}, [%4];"
                 : "=r"(r0), "=r"(r1), "=r"(r2), "=r"(r3) : "r"(addr));
}
__device__ __forceinline__ void ldsm_x4t(unsigned addr, unsigned& r0, unsigned& r1,
                                         unsigned& r2, unsigned& r3) {
    asm volatile("ldmatrix.sync.aligned.m8n8.x4.trans.shared.b16 {%0,%1,%2,%3}, [%4];"
                 : "=r"(r0), "=r"(r1), "=r"(r2), "=r"(r3) : "r"(addr));
}
__device__ __forceinline__ void mma16816(float c[4], const unsigned a[4], const unsigned b[2]) {
    asm volatile(
        "mma.sync.aligned.m16n8k16.row.col.f32.bf16.bf16.f32 "
        "{%0,%1,%2,%3}, {%4,%5,%6,%7}, {%8,%9}, {%0,%1,%2,%3};"
        : "+f"(c[0]), "+f"(c[1]), "+f"(c[2]), "+f"(c[3])
        : "r"(a[0]), "r"(a[1]), "r"(a[2]), "r"(a[3]), "r"(b[0]), "r"(b[1]));
}
__device__ __forceinline__ void split_bf(float x, __nv_bfloat16& h, __nv_bfloat16& l) {
    h = __float2bfloat16(x);
    l = __float2bfloat16(x - __bfloat162float(h));
}

// ---------------- scratch (device globals) ---------------------------------
__device__ float g_h[MTOT*D];
__device__ float g_att[MTOT*D];
__device__ float g_q[MTOT*D];
__device__ float g_k[MTOT*D];
__device__ float g_v[MTOT*D];
__device__ float g_ff[MTOT*FF];
__device__ float g_pool[BATCH*D];
__device__ float g_pooled[BATCH*D];

__device__ __forceinline__ float gelu_exact(float x) {
    return 0.5f * x * (1.0f + erff(x * 0.70710678118654752f));
}

// ============================================================================
// Tensor-core GEMM, bf16x3 (fp32-accurate). BM=128, BN=64, BK=32, 256 thr.
// 8 warps in 4x2; warp tile 32x32 (2 m16-tiles x 4 n8-tiles).
// mode 0: A[M,192] x Wqkv[3,192,192] (+bias) -> scatter q/k/v [B,H,S,Dh]
// mode 1: A[M,192] x W[192,576] (+bias, GELU) -> of
// mode 2: per-roi tokenizer: x rows x roi_W[roi] (+bias) -> raw tok
// mode 3: A[M,K] x W[K,192] (+bias) -> raw C
// ============================================================================
__global__ __launch_bounds__(256) void mma_gemm_kernel(
    const float* __restrict__ A, const float* __restrict__ W,
    const float* __restrict__ bias,
    float* __restrict__ oq, float* __restrict__ ok, float* __restrict__ ov,
    float* __restrict__ of, int mode, int K, int lda)
{
    __shared__ __nv_bfloat16 AsH[128][40];
    __shared__ __nv_bfloat16 AsL[128][40];
    __shared__ __nv_bfloat16 BsH[32][72];
    __shared__ __nv_bfloat16 BsL[32][72];

    int m0 = blockIdx.x * 128, n0 = blockIdx.y * 64, roi = blockIdx.z;
    int t = threadIdx.x;
    int warp = t >> 5, lane = t & 31;
    int wm = warp >> 1, wn = warp & 1;

    const float* Bp; int ldb, nb;
    if (mode == 0)      { int wh = n0 / D; Bp = W + (size_t)wh * D * D; nb = n0 - wh * D; ldb = D; }
    else if (mode == 1) { Bp = W; nb = n0; ldb = FF; }
    else if (mode == 2) { Bp = W + (size_t)roi * RD * D; nb = n0; ldb = D; }
    else                { Bp = W; nb = n0; ldb = D; }

    int acol0 = (mode == 2) ? roi * RD : 0;

    float acc[2][4][4] = {};

    for (int k0 = 0; k0 < K; k0 += 32) {
        // ---- A tile 128x32 ----
        if (mode == 2) {
            for (int p = t; p < 2048; p += 256) {
                int row = p >> 4, k2 = (p & 15) * 2;
                int k = k0 + k2;
                const float* ap = A + (size_t)(m0 + row) * lda + acol0;
                float x0 = (k < K) ? ap[k] : 0.f;
                float x1 = (k + 1 < K) ? ap[k + 1] : 0.f;
                __nv_bfloat16 h0, l0, h1, l1;
                split_bf(x0, h0, l0); split_bf(x1, h1, l1);
                *(__nv_bfloat162*)&AsH[row][k2] = __nv_bfloat162(h0, h1);
                *(__nv_bfloat162*)&AsL[row][k2] = __nv_bfloat162(l0, l1);
            }
        } else {
            for (int p = t; p < 2048; p += 256) {
                int row = p >> 4, k2 = (p & 15) * 2;
                float2 v = *(const float2*)(A + (size_t)(m0 + row) * lda + k0 + k2);
                __nv_bfloat16 h0, l0, h1, l1;
                split_bf(v.x, h0, l0); split_bf(v.y, h1, l1);
                *(__nv_bfloat162*)&AsH[row][k2] = __nv_bfloat162(h0, h1);
                *(__nv_bfloat162*)&AsL[row][k2] = __nv_bfloat162(l0, l1);
            }
        }
        // ---- B tile 32x64 ----
        for (int p = t; p < 1024; p += 256) {
            int k = p >> 5, n2 = (p & 31) * 2;
            float2 v = make_float2(0.f, 0.f);
            if (k0 + k < K)
                v = *(const float2*)(Bp + (size_t)(k0 + k) * ldb + nb + n2);
            __nv_bfloat16 h0, l0, h1, l1;
            split_bf(v.x, h0, l0); split_bf(v.y, h1, l1);
            *(__nv_bfloat162*)&BsH[k][n2] = __nv_bfloat162(h0, h1);
            *(__nv_bfloat162*)&BsL[k][n2] = __nv_bfloat162(l0, l1);
        }
        __syncthreads();

#pragma unroll
        for (int ks = 0; ks < 2; ++ks) {
            int kb = ks * 16;
            // A fragments (hi & lo) for 2 m-tiles
            unsigned aH[2][4], aL[2][4];
            int aro = ((lane >> 3) & 1) * 8 + (lane & 7);
            int aco = kb + (lane >> 4) * 8;
#pragma unroll
            for (int mt = 0; mt < 2; ++mt) {
                int r = wm * 32 + mt * 16 + aro;
                ldsm_x4(smem_u32(&AsH[r][aco]), aH[mt][0], aH[mt][1], aH[mt][2], aH[mt][3]);
                ldsm_x4(smem_u32(&AsL[r][aco]), aL[mt][0], aL[mt][1], aL[mt][2], aL[mt][3]);
            }
            // B fragments (hi & lo) for 4 n-tiles
            unsigned bH[4][2], bL[4][2];
            int bro = kb + ((lane >> 3) & 1) * 8 + (lane & 7);
            int bco = wn * 32 + (lane >> 4) * 8;
#pragma unroll
            for (int np = 0; np < 2; ++np) {
                unsigned r0, r1, r2, r3;
                ldsm_x4t(smem_u32(&BsH[bro][bco + np * 16]), r0, r1, r2, r3);
                bH[np*2][0] = r0; bH[np*2][1] = r1; bH[np*2+1][0] = r2; bH[np*2+1][1] = r3;
                ldsm_x4t(smem_u32(&BsL[bro][bco + np * 16]), r0, r1, r2, r3);
                bL[np*2][0] = r0; bL[np*2][1] = r1; bL[np*2+1][0] = r2; bL[np*2+1][1] = r3;
            }
#pragma unroll
            for (int mt = 0; mt < 2; ++mt)
#pragma unroll
                for (int nt = 0; nt < 4; ++nt) {
                    mma16816(acc[mt][nt], aH[mt], bH[nt]);
                    mma16816(acc[mt][nt], aH[mt], bL[nt]);
                    mma16816(acc[mt][nt], aL[mt], bH[nt]);
                }
        }
        __syncthreads();
    }

    // ---- epilogue ----
    int g = lane >> 2, tq = (lane & 3) * 2;
#pragma unroll
    for (int mt = 0; mt < 2; ++mt) {
        int r0 = m0 + wm * 32 + mt * 16 + g;
#pragma unroll
        for (int nt = 0; nt < 4; ++nt) {
            float* c = acc[mt][nt];
            if (mode == 0) {
                int wh = n0 / D;
                int colq = nb + wn * 32 + nt * 8 + tq;
                int hd = colq >> 5, dh = colq & 31;
                float2 bb = *(const float2*)(bias + wh * D + colq);
                float* o = (wh == 0) ? oq : ((wh == 1) ? ok : ov);
                int m = r0;
                int b = m / S, s = m - b * S;
                *(float2*)(o + (((size_t)b * NH + hd) * S + s) * DH + dh)
                    = make_float2(c[0] + bb.x, c[1] + bb.y);
                m = r0 + 8; b = m / S; s = m - b * S;
                *(float2*)(o + (((size_t)b * NH + hd) * S + s) * DH + dh)
                    = make_float2(c[2] + bb.x, c[3] + bb.y);
            } else if (mode == 1) {
                int col = n0 + wn * 32 + nt * 8 + tq;
                float2 bb = *(const float2*)(bias + col);
                *(float2*)(of + (size_t)r0 * FF + col)
                    = make_float2(gelu_exact(c[0] + bb.x), gelu_exact(c[1] + bb.y));
                *(float2*)(of + (size_t)(r0 + 8) * FF + col)
                    = make_float2(gelu_exact(c[2] + bb.x), gelu_exact(c[3] + bb.y));
            } else if (mode == 2) {
                int col = n0 + wn * 32 + nt * 8 + tq;
                float2 bb = *(const float2*)(bias + (size_t)roi * D + col);
                *(float2*)(of + ((size_t)r0 * S + roi) * D + col)
                    = make_float2(c[0] + bb.x, c[1] + bb.y);
                *(float2*)(of + ((size_t)(r0 + 8) * S + roi) * D + col)
                    = make_float2(c[2] + bb.x, c[3] + bb.y);
            } else {
                int col = n0 + wn * 32 + nt * 8 + tq;
                float2 bb = *(const float2*)(bias + col);
                *(float2*)(of + (size_t)r0 * D + col)
                    = make_float2(c[0] + bb.x, c[1] + bb.y);
                *(float2*)(of + (size_t)(r0 + 8) * D + col)
                    = make_float2(c[2] + bb.x, c[3] + bb.y);
            }
        }
    }
}

// ============================================================================
// add + LayerNorm pass: out = LN(raw + res) (warp per row)
// ============================================================================
__global__ void addln_kernel(const float* __restrict__ raw,
                             const float* __restrict__ res,
                             const float* __restrict__ lng,
                             const float* __restrict__ lnb,
                             float* __restrict__ out)
{
    int row = blockIdx.x * 8 + (threadIdx.x >> 5);
    int lane = threadIdx.x & 31;
    float vv[6];
    float sum = 0.f, sq = 0.f;
#pragma unroll
    for (int j = 0; j < 6; ++j) {
        int c = lane + 32 * j;
        vv[j] = raw[(size_t)row * D + c] + res[(size_t)row * D + c];
        sum += vv[j]; sq += vv[j] * vv[j];
    }
#pragma unroll
    for (int o = 16; o > 0; o >>= 1) {
        sum += __shfl_xor_sync(0xffffffffu, sum, o);
        sq  += __shfl_xor_sync(0xffffffffu, sq,  o);
    }
    float mean = sum * (1.f / D);
    float rstd = rsqrtf(sq * (1.f / D) - mean * mean + 1e-5f);
#pragma unroll
    for (int j = 0; j < 6; ++j) {
        int c = lane + 32 * j;
        out[(size_t)row * D + c] = (vv[j] - mean) * rstd * lng[c] + lnb[c];
    }
}

// ============================================================================
// token epilogue: per-roi LN + GELU + pos_emb (warp per row)
// ============================================================================
__global__ void tok_finish_kernel(const float* __restrict__ raw,
                                  const float* __restrict__ lng,
                                  const float* __restrict__ lnb,
                                  const float* __restrict__ pos,
                                  float* __restrict__ out)
{
    int row = blockIdx.x * 8 + (threadIdx.x >> 5);
    int roi = row % S;
    int lane = threadIdx.x & 31;
    float vv[6];
    float sum = 0.f, sq = 0.f;
#pragma unroll
    for (int j = 0; j < 6; ++j) {
        vv[j] = raw[(size_t)row * D + lane + 32 * j];
        sum += vv[j]; sq += vv[j] * vv[j];
    }
#pragma unroll
    for (int o = 16; o > 0; o >>= 1) {
        sum += __shfl_xor_sync(0xffffffffu, sum, o);
        sq  += __shfl_xor_sync(0xffffffffu, sq,  o);
    }
    float mean = sum * (1.f / D);
    float rstd = rsqrtf(sq * (1.f / D) - mean * mean + 1e-5f);
#pragma unroll
    for (int j = 0; j < 6; ++j) {
        int c = lane + 32 * j;
        float v = (vv[j] - mean) * rstd * lng[(size_t)roi * D + c] + lnb[(size_t)roi * D + c];
        out[(size_t)row * D + c] = gelu_exact(v) + pos[(size_t)roi * D + c];
    }
}

// ============================================================================
// attention (FFMA2, one-pass softmax; scores O(1) for this net)
// ============================================================================
__global__ __launch_bounds__(256) void attn_kernel(
    const float* __restrict__ q,
    const float* __restrict__ k,
    const float* __restrict__ v,
    float* __restrict__ out)
{
    __shared__ float Ks[100][DH];
    __shared__ float Vs[100][DH];
    int bh = blockIdx.x;
    int b = bh / NH, hd = bh % NH;
    size_t base = (size_t)bh * S * DH;
    int t = threadIdx.x;

    ull qp2[16];
    if (t < S) {
#pragma unroll
        for (int c4 = 0; c4 < DH; c4 += 4) {
            float4 x = *(const float4*)(q + base + (size_t)t * DH + c4);
            qp2[(c4 >> 1) + 0] = pack2(x.x * 0.17677669529663687f, x.y * 0.17677669529663687f);
            qp2[(c4 >> 1) + 1] = pack2(x.z * 0.17677669529663687f, x.w * 0.17677669529663687f);
        }
    }

    float l = 0.f;
    ull o2[16] = {};

#pragma unroll
    for (int tile = 0; tile < 2; ++tile) {
        int s0 = tile * 100;
        __syncthreads();
        for (int i = t; i < 800; i += 256) {
            int r = i >> 3, c4 = (i & 7) * 4;
            *(float4*)&Ks[r][c4] = *(const float4*)(k + base + (size_t)(s0 + r) * DH + c4);
            *(float4*)&Vs[r][c4] = *(const float4*)(v + base + (size_t)(s0 + r) * DH + c4);
        }
        __syncthreads();
        if (t < S) {
            for (int s = 0; s < 100; ++s) {
                ull sc2 = 0;
#pragma unroll
                for (int c4 = 0; c4 < DH; c4 += 4) {
                    ulonglong2 kk = *(const ulonglong2*)&Ks[s][c4];
                    fma2(sc2, qp2[(c4 >> 1) + 0], kk.x);
                    fma2(sc2, qp2[(c4 >> 1) + 1], kk.y);
                }
                float2 sp = unpk(sc2);
                float e = __expf(sp.x + sp.y);
                l += e;
                ull eb = bcast2(e);
#pragma unroll
                for (int c4 = 0; c4 < DH; c4 += 4) {
                    ulonglong2 vv = *(const ulonglong2*)&Vs[s][c4];
                    fma2(o2[(c4 >> 1) + 0], eb, vv.x);
                    fma2(o2[(c4 >> 1) + 1], eb, vv.y);
                }
            }
        }
    }

    if (t < S) {
        float inv = 1.f / l;
        float* op = out + ((size_t)b * S + t) * D + hd * DH;
#pragma unroll
        for (int c4 = 0; c4 < DH; c4 += 4) {
            float2 u0 = unpk(o2[(c4 >> 1) + 0]);
            float2 u1 = unpk(o2[(c4 >> 1) + 1]);
            *(float4*)(op + c4) = make_float4(u0.x * inv, u0.y * inv, u1.x * inv, u1.y * inv);
        }
    }
}

// ---------------- pooled attention (Q=1 via linearity) ---------------------
__global__ void pool_attn_kernel(const float* __restrict__ q,
                                 const float* __restrict__ k,
                                 const float* __restrict__ v,
                                 float* __restrict__ out)
{
    __shared__ float qm[DH];
    __shared__ float sc[S];
    __shared__ float red[2];
    int bh = blockIdx.x;
    int b = bh / NH, hd = bh % NH;
    size_t base = (size_t)bh * S * DH;
    int t = threadIdx.x;
    if (t < DH) {
        float s = 0.f;
        for (int j = 0; j < S; ++j) s += q[base + j * DH + t];
        qm[t] = s * (1.f / S) * 0.17677669529663687f;
    }
    __syncthreads();
    if (t < S) {
        float x = 0.f;
#pragma unroll
        for (int i = 0; i < DH; ++i) x += qm[i] * k[base + t * DH + i];
        sc[t] = x;
    }
    __syncthreads();
    if (t == 0) {
        float mx = -1e30f;
        for (int s = 0; s < S; ++s) mx = fmaxf(mx, sc[s]);
        red[0] = mx;
    }
    __syncthreads();
    if (t < S) sc[t] = __expf(sc[t] - red[0]);
    __syncthreads();
    if (t == 0) {
        float l = 0.f;
        for (int s = 0; s < S; ++s) l += sc[s];
        red[1] = 1.f / l;
    }
    __syncthreads();
    if (t < DH) {
        float o = 0.f;
        for (int s = 0; s < S; ++s) o += sc[s] * v[base + s * DH + t];
        out[(size_t)b * D + hd * DH + t] = o * red[1];
    }
}

// ---------------- pooled projection ----------------------------------------
__global__ void pool_proj_kernel(const float* __restrict__ in,
                                 const float* __restrict__ W,
                                 const float* __restrict__ bias,
                                 float* __restrict__ out)
{
    __shared__ float row[D];
    int b = blockIdx.x, d = threadIdx.x;
    row[d] = in[(size_t)b * D + d];
    __syncthreads();
    float s = bias[d];
    for (int k = 0; k < D; ++k) s += row[k] * W[(size_t)k * D + d];
    out[(size_t)b * D + d] = s;
}

// ---------------- classifier head ------------------------------------------
__global__ void cls_kernel(const float* __restrict__ in,
                           const float* __restrict__ g,  const float* __restrict__ bt,
                           const float* __restrict__ W1, const float* __restrict__ b1,
                           const float* __restrict__ W2, const float* __restrict__ b2,
                           const float* __restrict__ W3, const float* __restrict__ b3,
                           float* __restrict__ out)
{
    __shared__ float z[D];
    __shared__ float z1[96];
    __shared__ float z2[48];
    __shared__ float red[2];
    int b = blockIdx.x, t = threadIdx.x;
    float v = in[(size_t)b * D + t];
    z[t] = v;
    __syncthreads();
    if (t == 0) {
        float s = 0.f, sq = 0.f;
        for (int i = 0; i < D; ++i) { s += z[i]; sq += z[i] * z[i]; }
        float m = s / D;
        red[0] = m;
        red[1] = rsqrtf(sq / D - m * m + 1e-5f);
    }
    __syncthreads();
    z[t] = (v - red[0]) * red[1] * g[t] + bt[t];
    __syncthreads();
    if (t < 96) {
        float a = b1[t];
        for (int k = 0; k < D; ++k) a += z[k] * W1[k * 96 + t];
        z1[t] = gelu_exact(a);
    }
    __syncthreads();
    if (t < 48) {
        float a = b2[t];
        for (int k = 0; k < 96; ++k) a += z1[k] * W2[k * 48 + t];
        z2[t] = gelu_exact(a);
    }
    __syncthreads();
    if (t < 2) {
        float a = b3[t];
        for (int k = 0; k < 48; ++k) a += z2[k] * W3[k * 2 + t];
        out[(size_t)b * 2 + t] = a;
    }
}

// ---------------- launch ----------------------------------------------------
extern "C" void kernel_launch(void* const* d_in, const int* in_sizes, int n_in,
                              void* d_out, int out_size)
{
    const float* x        = (const float*)d_in[0];
    const float* roi_W    = (const float*)d_in[1];
    const float* roi_b    = (const float*)d_in[2];
    const float* roi_lng  = (const float*)d_in[3];
    const float* roi_lnb  = (const float*)d_in[4];
    const float* pos_emb  = (const float*)d_in[5];
    const float* enc_Wqkv = (const float*)d_in[6];
    const float* enc_bqkv = (const float*)d_in[7];
    const float* enc_Wo   = (const float*)d_in[8];
    const float* enc_bo   = (const float*)d_in[9];
    const float* enc_ln1g = (const float*)d_in[10];
    const float* enc_ln1b = (const float*)d_in[11];
    const float* enc_W1   = (const float*)d_in[12];
    const float* enc_b1   = (const float*)d_in[13];
    const float* enc_W2   = (const float*)d_in[14];
    const float* enc_b2   = (const float*)d_in[15];
    const float* enc_ln2g = (const float*)d_in[16];
    const float* enc_ln2b = (const float*)d_in[17];
    const float* pool_Wqkv= (const float*)d_in[18];
    const float* pool_bqkv= (const float*)d_in[19];
    const float* pool_Wo  = (const float*)d_in[20];
    const float* pool_bo  = (const float*)d_in[21];
    const float* cls_lng  = (const float*)d_in[22];
    const float* cls_lnb  = (const float*)d_in[23];
    const float* cls_W1   = (const float*)d_in[24];
    const float* cls_b1   = (const float*)d_in[25];
    const float* cls_W2   = (const float*)d_in[26];
    const float* cls_b2   = (const float*)d_in[27];
    const float* cls_W3   = (const float*)d_in[28];
    const float* cls_b3   = (const float*)d_in[29];
    float* out = (float*)d_out;

    float *h, *att, *q, *k, *v, *ff, *pool, *pooled;
    cudaGetSymbolAddress((void**)&h,      g_h);
    cudaGetSymbolAddress((void**)&att,    g_att);
    cudaGetSymbolAddress((void**)&q,      g_q);
    cudaGetSymbolAddress((void**)&k,      g_k);
    cudaGetSymbolAddress((void**)&v,      g_v);
    cudaGetSymbolAddress((void**)&ff,     g_ff);
    cudaGetSymbolAddress((void**)&pool,   g_pool);
    cudaGetSymbolAddress((void**)&pooled, g_pooled);

    // tokenizer: per-roi GEMM (raw -> att), then LN + GELU + pos
    mma_gemm_kernel<<<dim3(2, 3, 200), 256>>>(x, roi_W, roi_b,
                                              nullptr, nullptr, nullptr, att,
                                              2, RD, S * RD);
    tok_finish_kernel<<<MTOT / 8, 256>>>(att, roi_lng, roi_lnb, pos_emb, h);

    for (int l = 0; l < NL; ++l) {
        // QKV
        mma_gemm_kernel<<<dim3(MTOT / 128, 9, 1), 256>>>(h,
            enc_Wqkv + (size_t)l * 3 * D * D, enc_bqkv + (size_t)l * 3 * D,
            q, k, v, nullptr, 0, D, D);
        attn_kernel<<<BATCH * NH, 256>>>(q, k, v, att);
        // attn out projection -> raw (ff scratch), then add+LN
        mma_gemm_kernel<<<dim3(MTOT / 128, 3, 1), 256>>>(att,
            enc_Wo + (size_t)l * D * D, enc_bo + l * D,
            nullptr, nullptr, nullptr, ff, 3, D, D);
        addln_kernel<<<MTOT / 8, 256>>>(ff, h, enc_ln1g + l * D, enc_ln1b + l * D, h);
        // FFN1 (+GELU)
        mma_gemm_kernel<<<dim3(MTOT / 128, 9, 1), 256>>>(h,
            enc_W1 + (size_t)l * D * FF, enc_b1 + l * FF,
            nullptr, nullptr, nullptr, ff, 1, D, D);
        // FFN2 -> raw (att scratch), then add+LN
        mma_gemm_kernel<<<dim3(MTOT / 128, 3, 1), 256>>>(ff,
            enc_W2 + (size_t)l * FF * D, enc_b2 + l * D,
            nullptr, nullptr, nullptr, att, 3, FF, FF);
        addln_kernel<<<MTOT / 8, 256>>>(att, h, enc_ln2g + l * D, enc_ln2b + l * D, h);
    }

    // pooling
    mma_gemm_kernel<<<dim3(MTOT / 128, 9, 1), 256>>>(h, pool_Wqkv, pool_bqkv,
                                                     q, k, v, nullptr, 0, D, D);
    pool_attn_kernel<<<BATCH * NH, 256>>>(q, k, v, pool);
    pool_proj_kernel<<<BATCH, 192>>>(pool, pool_Wo, pool_bo, pooled);

    // classifier
    cls_kernel<<<BATCH, 192>>>(pooled, cls_lng, cls_lnb, cls_W1, cls_b1,
                               cls_W2, cls_b2, cls_W3, cls_b3, out);
}

// round 5
// speedup vs baseline: 3.1316x; 1.2958x over previous
#include <cuda_runtime.h>
#include <cuda_bf16.h>
#include <math.h>

#define BATCH 256
#define S 200
#define D 192
#define NH 6
#define DH 32
#define NL 3
#define FF 576
#define RD 199
#define MTOT (BATCH*S)
#define XPAD 224

typedef unsigned long long ull;
typedef __nv_bfloat16 bf16;

// ---------------- f32x2 packed-FMA helpers (attention) ---------------------
__device__ __forceinline__ ull pack2(float x, float y) {
    ull r; asm("mov.b64 %0, {%1, %2};" : "=l"(r) : "f"(x), "f"(y)); return r;
}
__device__ __forceinline__ ull bcast2(float x) {
    ull r; asm("mov.b64 %0, {%1, %1};" : "=l"(r) : "f"(x)); return r;
}
__device__ __forceinline__ void fma2(ull& d, ull a, ull b) {
    asm("fma.rn.f32x2 %0, %1, %2, %0;" : "+l"(d) : "l"(a), "l"(b));
}
__device__ __forceinline__ float2 unpk(ull v) {
    float2 f; asm("mov.b64 {%0, %1}, %2;" : "=f"(f.x), "=f"(f.y) : "l"(v)); return f;
}

// ---------------- mma helpers -----------------------------------------------
__device__ __forceinline__ unsigned smem_u32(const void* p) {
    return (unsigned)__cvta_generic_to_shared(p);
}
__device__ __forceinline__ void ldsm_x4(unsigned addr, unsigned& r0, unsigned& r1,
                                        unsigned& r2, unsigned& r3) {
    asm volatile("ldmatrix.sync.aligned.m8n8.x4.shared.b16 {%0,%1,%2,%3}, [%4];"
                 : "=r"(r0), "=r"(r1), "=r"(r2), "=r"(r3) : "r"(addr));
}
__device__ __forceinline__ void ldsm_x4t(unsigned addr, unsigned& r0, unsigned& r1,
                                         unsigned& r2, unsigned& r3) {
    asm volatile("ldmatrix.sync.aligned.m8n8.x4.trans.shared.b16 {%0,%1,%2,%3}, [%4];"
                 : "=r"(r0), "=r"(r1), "=r"(r2), "=r"(r3) : "r"(addr));
}
__device__ __forceinline__ void mma16816(float c[4], const unsigned a[4], const unsigned b[2]) {
    asm volatile(
        "mma.sync.aligned.m16n8k16.row.col.f32.bf16.bf16.f32 "
        "{%0,%1,%2,%3}, {%4,%5,%6,%7}, {%8,%9}, {%0,%1,%2,%3};"
        : "+f"(c[0]), "+f"(c[1]), "+f"(c[2]), "+f"(c[3])
        : "r"(a[0]), "r"(a[1]), "r"(a[2]), "r"(a[3]), "r"(b[0]), "r"(b[1]));
}
__device__ __forceinline__ void split_bf(float x, bf16& h, bf16& l) {
    h = __float2bfloat16(x);
    l = __float2bfloat16(x - __bfloat162float(h));
}

// ---------------- scratch (device globals) ---------------------------------
__device__ float g_h[MTOT*D];          // fp32 residual stream
__device__ float g_raw[MTOT*D];        // fp32 raw GEMM output scratch
__device__ float g_q[MTOT*D];
__device__ float g_k[MTOT*D];
__device__ float g_v[MTOT*D];
__device__ float g_pool[BATCH*D];
__device__ float g_pooled[BATCH*D];

// bf16 hi/lo activation buffers
__device__ bf16 g_xh[200*BATCH*XPAD], g_xl[200*BATCH*XPAD];
__device__ bf16 g_hh[MTOT*D], g_hl[MTOT*D];
__device__ bf16 g_ah[MTOT*D], g_al[MTOT*D];
__device__ bf16 g_fh[MTOT*FF], g_fl[MTOT*FF];
// bf16 hi/lo weight buffers
__device__ bf16 g_rwh[200*RD*D], g_rwl[200*RD*D];
__device__ bf16 g_qkvh[NL*3*D*D], g_qkvl[NL*3*D*D];
__device__ bf16 g_woh[NL*D*D],   g_wol[NL*D*D];
__device__ bf16 g_w1h[NL*D*FF],  g_w1l[NL*D*FF];
__device__ bf16 g_w2h[NL*FF*D],  g_w2l[NL*FF*D];
__device__ bf16 g_pwh[3*D*D],    g_pwl[3*D*D];

__device__ __forceinline__ float gelu_exact(float x) {
    return 0.5f * x * (1.0f + erff(x * 0.70710678118654752f));
}

// ---------------- conversion kernels ----------------------------------------
__global__ void cvt_kernel(const float* __restrict__ in, bf16* __restrict__ hi,
                           bf16* __restrict__ lo, int n)
{
    int i = blockIdx.x * 256 + threadIdx.x;
    if (i < n) {
        bf16 h, l; split_bf(in[i], h, l);
        hi[i] = h; lo[i] = l;
    }
}

// x [B, 200*199] -> xr [roi][b][224] (zero padded)
__global__ void cvt_x_kernel(const float* __restrict__ x,
                             bf16* __restrict__ hi, bf16* __restrict__ lo)
{
    int i = blockIdx.x * 256 + threadIdx.x;
    if (i >= 200 * BATCH * XPAD) return;
    int k = i % XPAD; int tmp = i / XPAD;
    int b = tmp % BATCH; int roi = tmp / BATCH;
    float v = (k < RD) ? x[(size_t)b * (200 * RD) + roi * RD + k] : 0.f;
    bf16 h, l; split_bf(v, h, l);
    hi[i] = h; lo[i] = l;
}

// ============================================================================
// Tensor-core GEMM, bf16x3, pre-split inputs. BM=128, BN=64, BK=32, 256 thr.
// mode 0: QKV scatter; mode 1: FFN1 (+GELU) -> bf16 pair; mode 2: tokenizer;
// mode 3: raw fp32 C.
// ============================================================================
__global__ __launch_bounds__(256) void mma_gemm_kernel(
    const bf16* __restrict__ Ah, const bf16* __restrict__ Al,
    const bf16* __restrict__ Wh, const bf16* __restrict__ Wl,
    const float* __restrict__ bias,
    float* __restrict__ oq, float* __restrict__ ok, float* __restrict__ ov,
    float* __restrict__ of, bf16* __restrict__ obh, bf16* __restrict__ obl,
    int mode, int K, int lda)
{
    __shared__ bf16 AsH[128][40];
    __shared__ bf16 AsL[128][40];
    __shared__ bf16 BsH[32][72];
    __shared__ bf16 BsL[32][72];

    int m0 = blockIdx.x * 128, n0 = blockIdx.y * 64, roi = blockIdx.z;
    int t = threadIdx.x;
    int warp = t >> 5, lane = t & 31;
    int wm = warp >> 1, wn = warp & 1;

    const bf16 *Bph, *Bpl; int ldb, nb;
    if (mode == 0)      { int wh = n0 / D; Bph = Wh + (size_t)wh * D * D; Bpl = Wl + (size_t)wh * D * D; nb = n0 - wh * D; ldb = D; }
    else if (mode == 1) { Bph = Wh; Bpl = Wl; nb = n0; ldb = FF; }
    else if (mode == 2) { Bph = Wh + (size_t)roi * RD * D; Bpl = Wl + (size_t)roi * RD * D; nb = n0; ldb = D; }
    else                { Bph = Wh; Bpl = Wl; nb = n0; ldb = D; }

    if (mode == 2) {
        Ah += (size_t)roi * BATCH * XPAD;
        Al += (size_t)roi * BATCH * XPAD;
    }

    float acc[2][4][4] = {};

    for (int k0 = 0; k0 < K; k0 += 32) {
        // ---- A tile 128x32 bf16 (hi & lo), 4-elem vector copies ----
#pragma unroll
        for (int p = t; p < 1024; p += 256) {
            int row = p >> 3, c4 = (p & 7) * 4;
            size_t off = (size_t)(m0 + row) * lda + k0 + c4;
            *(uint2*)&AsH[row][c4] = *(const uint2*)(Ah + off);
            *(uint2*)&AsL[row][c4] = *(const uint2*)(Al + off);
        }
        // ---- B tile 32x64 ----
#pragma unroll
        for (int p = t; p < 512; p += 256) {
            int k = p >> 4, n4 = (p & 15) * 4;
            uint2 zh = make_uint2(0u, 0u), zl = make_uint2(0u, 0u);
            if (k0 + k < K) {
                size_t off = (size_t)(k0 + k) * ldb + nb + n4;
                zh = *(const uint2*)(Bph + off);
                zl = *(const uint2*)(Bpl + off);
            }
            *(uint2*)&BsH[k][n4] = zh;
            *(uint2*)&BsL[k][n4] = zl;
        }
        __syncthreads();

#pragma unroll
        for (int ks = 0; ks < 2; ++ks) {
            int kb = ks * 16;
            unsigned aH[2][4], aL[2][4];
            int aro = ((lane >> 3) & 1) * 8 + (lane & 7);
            int aco = kb + (lane >> 4) * 8;
#pragma unroll
            for (int mt = 0; mt < 2; ++mt) {
                int r = wm * 32 + mt * 16 + aro;
                ldsm_x4(smem_u32(&AsH[r][aco]), aH[mt][0], aH[mt][1], aH[mt][2], aH[mt][3]);
                ldsm_x4(smem_u32(&AsL[r][aco]), aL[mt][0], aL[mt][1], aL[mt][2], aL[mt][3]);
            }
            unsigned bH[4][2], bL[4][2];
            int bro = kb + ((lane >> 3) & 1) * 8 + (lane & 7);
            int bco = wn * 32 + (lane >> 4) * 8;
#pragma unroll
            for (int np = 0; np < 2; ++np) {
                unsigned r0, r1, r2, r3;
                ldsm_x4t(smem_u32(&BsH[bro][bco + np * 16]), r0, r1, r2, r3);
                bH[np*2][0] = r0; bH[np*2][1] = r1; bH[np*2+1][0] = r2; bH[np*2+1][1] = r3;
                ldsm_x4t(smem_u32(&BsL[bro][bco + np * 16]), r0, r1, r2, r3);
                bL[np*2][0] = r0; bL[np*2][1] = r1; bL[np*2+1][0] = r2; bL[np*2+1][1] = r3;
            }
#pragma unroll
            for (int mt = 0; mt < 2; ++mt)
#pragma unroll
                for (int nt = 0; nt < 4; ++nt) {
                    mma16816(acc[mt][nt], aH[mt], bH[nt]);
                    mma16816(acc[mt][nt], aH[mt], bL[nt]);
                    mma16816(acc[mt][nt], aL[mt], bH[nt]);
                }
        }
        __syncthreads();
    }

    // ---- epilogue ----
    int g = lane >> 2, tq = (lane & 3) * 2;
#pragma unroll
    for (int mt = 0; mt < 2; ++mt) {
        int r0 = m0 + wm * 32 + mt * 16 + g;
#pragma unroll
        for (int nt = 0; nt < 4; ++nt) {
            float* c = acc[mt][nt];
            if (mode == 0) {
                int wh = n0 / D;
                int colq = nb + wn * 32 + nt * 8 + tq;
                int hd = colq >> 5, dh = colq & 31;
                float2 bb = *(const float2*)(bias + wh * D + colq);
                float* o = (wh == 0) ? oq : ((wh == 1) ? ok : ov);
                int m = r0;
                int b = m / S, s = m - b * S;
                *(float2*)(o + (((size_t)b * NH + hd) * S + s) * DH + dh)
                    = make_float2(c[0] + bb.x, c[1] + bb.y);
                m = r0 + 8; b = m / S; s = m - b * S;
                *(float2*)(o + (((size_t)b * NH + hd) * S + s) * DH + dh)
                    = make_float2(c[2] + bb.x, c[3] + bb.y);
            } else if (mode == 1) {
                int col = n0 + wn * 32 + nt * 8 + tq;
                float2 bb = *(const float2*)(bias + col);
                float f0 = gelu_exact(c[0] + bb.x), f1 = gelu_exact(c[1] + bb.y);
                bf16 h0, l0, h1, l1;
                split_bf(f0, h0, l0); split_bf(f1, h1, l1);
                *(__nv_bfloat162*)(obh + (size_t)r0 * FF + col) = __nv_bfloat162(h0, h1);
                *(__nv_bfloat162*)(obl + (size_t)r0 * FF + col) = __nv_bfloat162(l0, l1);
                f0 = gelu_exact(c[2] + bb.x); f1 = gelu_exact(c[3] + bb.y);
                split_bf(f0, h0, l0); split_bf(f1, h1, l1);
                *(__nv_bfloat162*)(obh + (size_t)(r0 + 8) * FF + col) = __nv_bfloat162(h0, h1);
                *(__nv_bfloat162*)(obl + (size_t)(r0 + 8) * FF + col) = __nv_bfloat162(l0, l1);
            } else if (mode == 2) {
                int col = n0 + wn * 32 + nt * 8 + tq;
                float2 bb = *(const float2*)(bias + (size_t)roi * D + col);
                *(float2*)(of + ((size_t)r0 * S + roi) * D + col)
                    = make_float2(c[0] + bb.x, c[1] + bb.y);
                *(float2*)(of + ((size_t)(r0 + 8) * S + roi) * D + col)
                    = make_float2(c[2] + bb.x, c[3] + bb.y);
            } else {
                int col = n0 + wn * 32 + nt * 8 + tq;
                float2 bb = *(const float2*)(bias + col);
                *(float2*)(of + (size_t)r0 * D + col)
                    = make_float2(c[0] + bb.x, c[1] + bb.y);
                *(float2*)(of + (size_t)(r0 + 8) * D + col)
                    = make_float2(c[2] + bb.x, c[3] + bb.y);
            }
        }
    }
}

// ============================================================================
// add + LayerNorm: out = LN(raw + res) -> fp32 h + bf16 hi/lo
// ============================================================================
__global__ void addln_kernel(const float* __restrict__ raw,
                             const float* __restrict__ res,
                             const float* __restrict__ lng,
                             const float* __restrict__ lnb,
                             float* __restrict__ out,
                             bf16* __restrict__ oh, bf16* __restrict__ ol)
{
    int row = blockIdx.x * 8 + (threadIdx.x >> 5);
    int lane = threadIdx.x & 31;
    float vv[6];
    float sum = 0.f, sq = 0.f;
#pragma unroll
    for (int j = 0; j < 6; ++j) {
        int c = lane + 32 * j;
        vv[j] = raw[(size_t)row * D + c] + res[(size_t)row * D + c];
        sum += vv[j]; sq += vv[j] * vv[j];
    }
#pragma unroll
    for (int o = 16; o > 0; o >>= 1) {
        sum += __shfl_xor_sync(0xffffffffu, sum, o);
        sq  += __shfl_xor_sync(0xffffffffu, sq,  o);
    }
    float mean = sum * (1.f / D);
    float rstd = rsqrtf(sq * (1.f / D) - mean * mean + 1e-5f);
#pragma unroll
    for (int j = 0; j < 6; ++j) {
        int c = lane + 32 * j;
        float val = (vv[j] - mean) * rstd * lng[c] + lnb[c];
        out[(size_t)row * D + c] = val;
        bf16 h, l; split_bf(val, h, l);
        oh[(size_t)row * D + c] = h; ol[(size_t)row * D + c] = l;
    }
}

// ============================================================================
// token epilogue: per-roi LN + GELU + pos -> fp32 h + bf16 hi/lo
// ============================================================================
__global__ void tok_finish_kernel(const float* __restrict__ raw,
                                  const float* __restrict__ lng,
                                  const float* __restrict__ lnb,
                                  const float* __restrict__ pos,
                                  float* __restrict__ out,
                                  bf16* __restrict__ oh, bf16* __restrict__ ol)
{
    int row = blockIdx.x * 8 + (threadIdx.x >> 5);
    int roi = row % S;
    int lane = threadIdx.x & 31;
    float vv[6];
    float sum = 0.f, sq = 0.f;
#pragma unroll
    for (int j = 0; j < 6; ++j) {
        vv[j] = raw[(size_t)row * D + lane + 32 * j];
        sum += vv[j]; sq += vv[j] * vv[j];
    }
#pragma unroll
    for (int o = 16; o > 0; o >>= 1) {
        sum += __shfl_xor_sync(0xffffffffu, sum, o);
        sq  += __shfl_xor_sync(0xffffffffu, sq,  o);
    }
    float mean = sum * (1.f / D);
    float rstd = rsqrtf(sq * (1.f / D) - mean * mean + 1e-5f);
#pragma unroll
    for (int j = 0; j < 6; ++j) {
        int c = lane + 32 * j;
        float v = (vv[j] - mean) * rstd * lng[(size_t)roi * D + c] + lnb[(size_t)roi * D + c];
        float val = gelu_exact(v) + pos[(size_t)roi * D + c];
        out[(size_t)row * D + c] = val;
        bf16 h, l; split_bf(val, h, l);
        oh[(size_t)row * D + c] = h; ol[(size_t)row * D + c] = l;
    }
}

// ============================================================================
// attention (FFMA2, 2-key unroll, one-pass softmax) -> bf16 hi/lo output
// ============================================================================
__global__ __launch_bounds__(256) void attn_kernel(
    const float* __restrict__ q,
    const float* __restrict__ k,
    const float* __restrict__ v,
    bf16* __restrict__ oh, bf16* __restrict__ ol)
{
    __shared__ float Ks[100][DH];
    __shared__ float Vs[100][DH];
    int bh = blockIdx.x;
    int b = bh / NH, hd = bh % NH;
    size_t base = (size_t)bh * S * DH;
    int t = threadIdx.x;

    ull qp2[16];
    if (t < S) {
#pragma unroll
        for (int c4 = 0; c4 < DH; c4 += 4) {
            float4 x = *(const float4*)(q + base + (size_t)t * DH + c4);
            qp2[(c4 >> 1) + 0] = pack2(x.x * 0.17677669529663687f, x.y * 0.17677669529663687f);
            qp2[(c4 >> 1) + 1] = pack2(x.z * 0.17677669529663687f, x.w * 0.17677669529663687f);
        }
    }

    float l = 0.f;
    ull o2[16] = {};

#pragma unroll
    for (int tile = 0; tile < 2; ++tile) {
        int s0 = tile * 100;
        __syncthreads();
        for (int i = t; i < 800; i += 256) {
            int r = i >> 3, c4 = (i & 7) * 4;
            *(float4*)&Ks[r][c4] = *(const float4*)(k + base + (size_t)(s0 + r) * DH + c4);
            *(float4*)&Vs[r][c4] = *(const float4*)(v + base + (size_t)(s0 + r) * DH + c4);
        }
        __syncthreads();
        if (t < S) {
            for (int s = 0; s < 100; s += 2) {
                ull sa = 0, sb = 0;
#pragma unroll
                for (int c4 = 0; c4 < DH; c4 += 4) {
                    ulonglong2 ka = *(const ulonglong2*)&Ks[s][c4];
                    ulonglong2 kb = *(const ulonglong2*)&Ks[s + 1][c4];
                    fma2(sa, qp2[(c4 >> 1) + 0], ka.x);
                    fma2(sb, qp2[(c4 >> 1) + 0], kb.x);
                    fma2(sa, qp2[(c4 >> 1) + 1], ka.y);
                    fma2(sb, qp2[(c4 >> 1) + 1], kb.y);
                }
                float2 spa = unpk(sa), spb = unpk(sb);
                float ea = __expf(spa.x + spa.y);
                float eb = __expf(spb.x + spb.y);
                l += ea + eb;
                ull ba = bcast2(ea), bb = bcast2(eb);
#pragma unroll
                for (int c4 = 0; c4 < DH; c4 += 4) {
                    ulonglong2 va = *(const ulonglong2*)&Vs[s][c4];
                    ulonglong2 vb = *(const ulonglong2*)&Vs[s + 1][c4];
                    fma2(o2[(c4 >> 1) + 0], ba, va.x);
                    fma2(o2[(c4 >> 1) + 1], ba, va.y);
                    fma2(o2[(c4 >> 1) + 0], bb, vb.x);
                    fma2(o2[(c4 >> 1) + 1], bb, vb.y);
                }
            }
        }
    }

    if (t < S) {
        float inv = 1.f / l;
        size_t off = ((size_t)b * S + t) * D + hd * DH;
#pragma unroll
        for (int c4 = 0; c4 < DH; c4 += 4) {
            float2 u0 = unpk(o2[(c4 >> 1) + 0]);
            float2 u1 = unpk(o2[(c4 >> 1) + 1]);
            float f0 = u0.x * inv, f1 = u0.y * inv, f2 = u1.x * inv, f3 = u1.y * inv;
            bf16 h0, l0, h1, l1, h2, l2, h3, l3;
            split_bf(f0, h0, l0); split_bf(f1, h1, l1);
            split_bf(f2, h2, l2); split_bf(f3, h3, l3);
            *(__nv_bfloat162*)(oh + off + c4)     = __nv_bfloat162(h0, h1);
            *(__nv_bfloat162*)(oh + off + c4 + 2) = __nv_bfloat162(h2, h3);
            *(__nv_bfloat162*)(ol + off + c4)     = __nv_bfloat162(l0, l1);
            *(__nv_bfloat162*)(ol + off + c4 + 2) = __nv_bfloat162(l2, l3);
        }
    }
}

// ---------------- pooled attention (Q=1 via linearity) ---------------------
__global__ void pool_attn_kernel(const float* __restrict__ q,
                                 const float* __restrict__ k,
                                 const float* __restrict__ v,
                                 float* __restrict__ out)
{
    __shared__ float qm[DH];
    __shared__ float sc[S];
    __shared__ float red[2];
    int bh = blockIdx.x;
    int b = bh / NH, hd = bh % NH;
    size_t base = (size_t)bh * S * DH;
    int t = threadIdx.x;
    if (t < DH) {
        float s = 0.f;
        for (int j = 0; j < S; ++j) s += q[base + j * DH + t];
        qm[t] = s * (1.f / S) * 0.17677669529663687f;
    }
    __syncthreads();
    if (t < S) {
        float x = 0.f;
#pragma unroll
        for (int i = 0; i < DH; ++i) x += qm[i] * k[base + t * DH + i];
        sc[t] = x;
    }
    __syncthreads();
    if (t == 0) {
        float mx = -1e30f;
        for (int s = 0; s < S; ++s) mx = fmaxf(mx, sc[s]);
        red[0] = mx;
    }
    __syncthreads();
    if (t < S) sc[t] = __expf(sc[t] - red[0]);
    __syncthreads();
    if (t == 0) {
        float l = 0.f;
        for (int s = 0; s < S; ++s) l += sc[s];
        red[1] = 1.f / l;
    }
    __syncthreads();
    if (t < DH) {
        float o = 0.f;
        for (int s = 0; s < S; ++s) o += sc[s] * v[base + s * DH + t];
        out[(size_t)b * D + hd * DH + t] = o * red[1];
    }
}

// ---------------- pooled projection ----------------------------------------
__global__ void pool_proj_kernel(const float* __restrict__ in,
                                 const float* __restrict__ W,
                                 const float* __restrict__ bias,
                                 float* __restrict__ out)
{
    __shared__ float row[D];
    int b = blockIdx.x, d = threadIdx.x;
    row[d] = in[(size_t)b * D + d];
    __syncthreads();
    float s = bias[d];
    for (int k = 0; k < D; ++k) s += row[k] * W[(size_t)k * D + d];
    out[(size_t)b * D + d] = s;
}

// ---------------- classifier head ------------------------------------------
__global__ void cls_kernel(const float* __restrict__ in,
                           const float* __restrict__ g,  const float* __restrict__ bt,
                           const float* __restrict__ W1, const float* __restrict__ b1,
                           const float* __restrict__ W2, const float* __restrict__ b2,
                           const float* __restrict__ W3, const float* __restrict__ b3,
                           float* __restrict__ out)
{
    __shared__ float z[D];
    __shared__ float z1[96];
    __shared__ float z2[48];
    __shared__ float red[2];
    int b = blockIdx.x, t = threadIdx.x;
    float v = in[(size_t)b * D + t];
    z[t] = v;
    __syncthreads();
    if (t == 0) {
        float s = 0.f, sq = 0.f;
        for (int i = 0; i < D; ++i) { s += z[i]; sq += z[i] * z[i]; }
        float m = s / D;
        red[0] = m;
        red[1] = rsqrtf(sq / D - m * m + 1e-5f);
    }
    __syncthreads();
    z[t] = (v - red[0]) * red[1] * g[t] + bt[t];
    __syncthreads();
    if (t < 96) {
        float a = b1[t];
        for (int k = 0; k < D; ++k) a += z[k] * W1[k * 96 + t];
        z1[t] = gelu_exact(a);
    }
    __syncthreads();
    if (t < 48) {
        float a = b2[t];
        for (int k = 0; k < 96; ++k) a += z1[k] * W2[k * 48 + t];
        z2[t] = gelu_exact(a);
    }
    __syncthreads();
    if (t < 2) {
        float a = b3[t];
        for (int k = 0; k < 48; ++k) a += z2[k] * W3[k * 2 + t];
        out[(size_t)b * 2 + t] = a;
    }
}

// ---------------- launch ----------------------------------------------------
extern "C" void kernel_launch(void* const* d_in, const int* in_sizes, int n_in,
                              void* d_out, int out_size)
{
    const float* x        = (const float*)d_in[0];
    const float* roi_W    = (const float*)d_in[1];
    const float* roi_b    = (const float*)d_in[2];
    const float* roi_lng  = (const float*)d_in[3];
    const float* roi_lnb  = (const float*)d_in[4];
    const float* pos_emb  = (const float*)d_in[5];
    const float* enc_Wqkv = (const float*)d_in[6];
    const float* enc_bqkv = (const float*)d_in[7];
    const float* enc_Wo   = (const float*)d_in[8];
    const float* enc_bo   = (const float*)d_in[9];
    const float* enc_ln1g = (const float*)d_in[10];
    const float* enc_ln1b = (const float*)d_in[11];
    const float* enc_W1   = (const float*)d_in[12];
    const float* enc_b1   = (const float*)d_in[13];
    const float* enc_W2   = (const float*)d_in[14];
    const float* enc_b2   = (const float*)d_in[15];
    const float* enc_ln2g = (const float*)d_in[16];
    const float* enc_ln2b = (const float*)d_in[17];
    const float* pool_Wqkv= (const float*)d_in[18];
    const float* pool_bqkv= (const float*)d_in[19];
    const float* pool_Wo  = (const float*)d_in[20];
    const float* pool_bo  = (const float*)d_in[21];
    const float* cls_lng  = (const float*)d_in[22];
    const float* cls_lnb  = (const float*)d_in[23];
    const float* cls_W1   = (const float*)d_in[24];
    const float* cls_b1   = (const float*)d_in[25];
    const float* cls_W2   = (const float*)d_in[26];
    const float* cls_b2   = (const float*)d_in[27];
    const float* cls_W3   = (const float*)d_in[28];
    const float* cls_b3   = (const float*)d_in[29];
    float* out = (float*)d_out;

    float *h, *raw, *q, *k, *v, *pool, *pooled;
    bf16 *xh, *xl, *hh, *hl, *ah, *al, *fh, *fl;
    bf16 *rwh, *rwl, *qkvh, *qkvl, *woh, *wol, *w1h, *w1l, *w2h, *w2l, *pwh, *pwl;
    cudaGetSymbolAddress((void**)&h,    g_h);
    cudaGetSymbolAddress((void**)&raw,  g_raw);
    cudaGetSymbolAddress((void**)&q,    g_q);
    cudaGetSymbolAddress((void**)&k,    g_k);
    cudaGetSymbolAddress((void**)&v,    g_v);
    cudaGetSymbolAddress((void**)&pool, g_pool);
    cudaGetSymbolAddress((void**)&pooled, g_pooled);
    cudaGetSymbolAddress((void**)&xh, g_xh);   cudaGetSymbolAddress((void**)&xl, g_xl);
    cudaGetSymbolAddress((void**)&hh, g_hh);   cudaGetSymbolAddress((void**)&hl, g_hl);
    cudaGetSymbolAddress((void**)&ah, g_ah);   cudaGetSymbolAddress((void**)&al, g_al);
    cudaGetSymbolAddress((void**)&fh, g_fh);   cudaGetSymbolAddress((void**)&fl, g_fl);
    cudaGetSymbolAddress((void**)&rwh, g_rwh); cudaGetSymbolAddress((void**)&rwl, g_rwl);
    cudaGetSymbolAddress((void**)&qkvh, g_qkvh); cudaGetSymbolAddress((void**)&qkvl, g_qkvl);
    cudaGetSymbolAddress((void**)&woh, g_woh); cudaGetSymbolAddress((void**)&wol, g_wol);
    cudaGetSymbolAddress((void**)&w1h, g_w1h); cudaGetSymbolAddress((void**)&w1l, g_w1l);
    cudaGetSymbolAddress((void**)&w2h, g_w2h); cudaGetSymbolAddress((void**)&w2l, g_w2l);
    cudaGetSymbolAddress((void**)&pwh, g_pwh); cudaGetSymbolAddress((void**)&pwl, g_pwl);

    // ---- pre-split weights & x ----
    cvt_x_kernel<<<(200 * BATCH * XPAD + 255) / 256, 256>>>(x, xh, xl);
    cvt_kernel<<<(200 * RD * D + 255) / 256, 256>>>(roi_W, rwh, rwl, 200 * RD * D);
    cvt_kernel<<<(NL * 3 * D * D + 255) / 256, 256>>>(enc_Wqkv, qkvh, qkvl, NL * 3 * D * D);
    cvt_kernel<<<(NL * D * D + 255) / 256, 256>>>(enc_Wo, woh, wol, NL * D * D);
    cvt_kernel<<<(NL * D * FF + 255) / 256, 256>>>(enc_W1, w1h, w1l, NL * D * FF);
    cvt_kernel<<<(NL * FF * D + 255) / 256, 256>>>(enc_W2, w2h, w2l, NL * FF * D);
    cvt_kernel<<<(3 * D * D + 255) / 256, 256>>>(pool_Wqkv, pwh, pwl, 3 * D * D);

    // ---- tokenizer ----
    mma_gemm_kernel<<<dim3(2, 3, 200), 256>>>(xh, xl, rwh, rwl, roi_b,
        nullptr, nullptr, nullptr, raw, nullptr, nullptr, 2, RD, XPAD);
    tok_finish_kernel<<<MTOT / 8, 256>>>(raw, roi_lng, roi_lnb, pos_emb, h, hh, hl);

    // ---- encoder layers ----
    for (int l = 0; l < NL; ++l) {
        mma_gemm_kernel<<<dim3(MTOT / 128, 9, 1), 256>>>(hh, hl,
            qkvh + (size_t)l * 3 * D * D, qkvl + (size_t)l * 3 * D * D,
            enc_bqkv + (size_t)l * 3 * D,
            q, k, v, nullptr, nullptr, nullptr, 0, D, D);
        attn_kernel<<<BATCH * NH, 256>>>(q, k, v, ah, al);
        mma_gemm_kernel<<<dim3(MTOT / 128, 3, 1), 256>>>(ah, al,
            woh + (size_t)l * D * D, wol + (size_t)l * D * D, enc_bo + l * D,
            nullptr, nullptr, nullptr, raw, nullptr, nullptr, 3, D, D);
        addln_kernel<<<MTOT / 8, 256>>>(raw, h, enc_ln1g + l * D, enc_ln1b + l * D, h, hh, hl);
        mma_gemm_kernel<<<dim3(MTOT / 128, 9, 1), 256>>>(hh, hl,
            w1h + (size_t)l * D * FF, w1l + (size_t)l * D * FF, enc_b1 + l * FF,
            nullptr, nullptr, nullptr, nullptr, fh, fl, 1, D, D);
        mma_gemm_kernel<<<dim3(MTOT / 128, 3, 1), 256>>>(fh, fl,
            w2h + (size_t)l * FF * D, w2l + (size_t)l * FF * D, enc_b2 + l * D,
            nullptr, nullptr, nullptr, raw, nullptr, nullptr, 3, FF, FF);
        addln_kernel<<<MTOT / 8, 256>>>(raw, h, enc_ln2g + l * D, enc_ln2b + l * D, h, hh, hl);
    }

    // ---- pooling ----
    mma_gemm_kernel<<<dim3(MTOT / 128, 9, 1), 256>>>(hh, hl, pwh, pwl, pool_bqkv,
        q, k, v, nullptr, nullptr, nullptr, 0, D, D);
    pool_attn_kernel<<<BATCH * NH, 256>>>(q, k, v, pool);
    pool_proj_kernel<<<BATCH, 192>>>(pool, pool_Wo, pool_bo, pooled);

    // ---- classifier ----
    cls_kernel<<<BATCH, 192>>>(pooled, cls_lng, cls_lnb, cls_W1, cls_b1,
                               cls_W2, cls_b2, cls_W3, cls_b3, out);
}

// round 7
// speedup vs baseline: 3.4698x; 1.1080x over previous
#include <cuda_runtime.h>
#include <cuda_bf16.h>
#include <math.h>

#define BATCH 256
#define S 200
#define D 192
#define NH 6
#define DH 32
#define NL 3
#define FF 576
#define RD 199
#define MTOT (BATCH*S)
#define XPAD 224

typedef __nv_bfloat16 bf16;

// ---------------- mma helpers -----------------------------------------------
__device__ __forceinline__ unsigned smem_u32(const void* p) {
    return (unsigned)__cvta_generic_to_shared(p);
}
__device__ __forceinline__ void ldsm_x4(unsigned addr, unsigned& r0, unsigned& r1,
                                        unsigned& r2, unsigned& r3) {
    asm volatile("ldmatrix.sync.aligned.m8n8.x4.shared.b16 {%0,%1,%2,%3}, [%4];"
                 : "=r"(r0), "=r"(r1), "=r"(r2), "=r"(r3) : "r"(addr));
}
__device__ __forceinline__ void ldsm_x4t(unsigned addr, unsigned& r0, unsigned& r1,
                                         unsigned& r2, unsigned& r3) {
    asm volatile("ldmatrix.sync.aligned.m8n8.x4.trans.shared.b16 {%0,%1,%2,%3}, [%4];"
                 : "=r"(r0), "=r"(r1), "=r"(r2), "=r"(r3) : "r"(addr));
}
__device__ __forceinline__ void mma16816(float c[4], const unsigned a[4], const unsigned b[2]) {
    asm volatile(
        "mma.sync.aligned.m16n8k16.row.col.f32.bf16.bf16.f32 "
        "{%0,%1,%2,%3}, {%4,%5,%6,%7}, {%8,%9}, {%0,%1,%2,%3};"
        : "+f"(c[0]), "+f"(c[1]), "+f"(c[2]), "+f"(c[3])
        : "r"(a[0]), "r"(a[1]), "r"(a[2]), "r"(a[3]), "r"(b[0]), "r"(b[1]));
}
__device__ __forceinline__ void split_bf(float x, bf16& h, bf16& l) {
    h = __float2bfloat16(x);
    l = __float2bfloat16(x - __bfloat162float(h));
}
__device__ __forceinline__ unsigned pack_bf2(bf16 a, bf16 b) {
    __nv_bfloat162 t(a, b);
    return *(unsigned*)&t;
}

// ---------------- scratch (device globals) ---------------------------------
__device__ float g_h[MTOT*D];
__device__ float g_raw[MTOT*D];
__device__ float g_q[MTOT*D];
__device__ float g_k[MTOT*D];
__device__ float g_v[MTOT*D];
__device__ float g_pool[BATCH*D];
__device__ float g_pooled[BATCH*D];

// bf16 hi/lo activation buffers
__device__ bf16 g_xh[200*BATCH*XPAD], g_xl[200*BATCH*XPAD];
__device__ bf16 g_hh[MTOT*D], g_hl[MTOT*D];
__device__ bf16 g_ah[MTOT*D], g_al[MTOT*D];
__device__ bf16 g_fh[MTOT*FF], g_fl[MTOT*FF];
// attention bf16 operand buffers
__device__ bf16 g_qbh[MTOT*D], g_qbl[MTOT*D];     // [bh][s][dh] (pre-scaled)
__device__ bf16 g_kth[MTOT*D], g_ktl[MTOT*D];     // [bh][dh][s]
__device__ bf16 g_vbh[MTOT*D], g_vbl[MTOT*D];     // [bh][s][dh]
// bf16 hi/lo weight buffers
__device__ bf16 g_rwh[200*RD*D], g_rwl[200*RD*D];
__device__ bf16 g_qkvh[NL*3*D*D], g_qkvl[NL*3*D*D];
__device__ bf16 g_woh[NL*D*D],   g_wol[NL*D*D];
__device__ bf16 g_w1h[NL*D*FF],  g_w1l[NL*D*FF];
__device__ bf16 g_w2h[NL*FF*D],  g_w2l[NL*FF*D];
__device__ bf16 g_pwh[3*D*D],    g_pwl[3*D*D];

__device__ __forceinline__ float gelu_exact(float x) {
    return 0.5f * x * (1.0f + erff(x * 0.70710678118654752f));
}

// ---------------- conversion kernels ----------------------------------------
__global__ void cvt_kernel(const float* __restrict__ in, bf16* __restrict__ hi,
                           bf16* __restrict__ lo, int n)
{
    int i = blockIdx.x * 256 + threadIdx.x;
    if (i < n) {
        bf16 h, l; split_bf(in[i], h, l);
        hi[i] = h; lo[i] = l;
    }
}

__global__ void cvt_x_kernel(const float* __restrict__ x,
                             bf16* __restrict__ hi, bf16* __restrict__ lo)
{
    int i = blockIdx.x * 256 + threadIdx.x;
    if (i >= 200 * BATCH * XPAD) return;
    int k = i % XPAD; int tmp = i / XPAD;
    int b = tmp % BATCH; int roi = tmp / BATCH;
    float v = (k < RD) ? x[(size_t)b * (200 * RD) + roi * RD + k] : 0.f;
    bf16 h, l; split_bf(v, h, l);
    hi[i] = h; lo[i] = l;
}

// ============================================================================
// Tensor-core GEMM, bf16x3, pre-split inputs. BM=128, BN=64, BK=32, 256 thr.
// mode 0: QKV fp32 scatter (pool); mode 1: FFN1 (+GELU) -> bf16 pair;
// mode 2: tokenizer; mode 3: raw fp32 C; mode 4: QKV bf16 scatter + K^T.
// ============================================================================
__global__ __launch_bounds__(256) void mma_gemm_kernel(
    const bf16* __restrict__ Ah, const bf16* __restrict__ Al,
    const bf16* __restrict__ Wh, const bf16* __restrict__ Wl,
    const float* __restrict__ bias,
    float* __restrict__ oq, float* __restrict__ ok, float* __restrict__ ov,
    float* __restrict__ of, bf16* __restrict__ obh, bf16* __restrict__ obl,
    bf16* __restrict__ xqh, bf16* __restrict__ xql,
    bf16* __restrict__ xkh, bf16* __restrict__ xkl,
    bf16* __restrict__ xvh, bf16* __restrict__ xvl,
    int mode, int K, int lda)
{
    __shared__ bf16 AsH[128][40];
    __shared__ bf16 AsL[128][40];
    __shared__ bf16 BsH[32][72];
    __shared__ bf16 BsL[32][72];

    int m0 = blockIdx.x * 128, n0 = blockIdx.y * 64, roi = blockIdx.z;
    int t = threadIdx.x;
    int warp = t >> 5, lane = t & 31;
    int wm = warp >> 1, wn = warp & 1;

    const bf16 *Bph, *Bpl; int ldb, nb;
    if (mode == 0 || mode == 4) {
        int wh = n0 / D;
        Bph = Wh + (size_t)wh * D * D; Bpl = Wl + (size_t)wh * D * D;
        nb = n0 - wh * D; ldb = D;
    } else if (mode == 1) { Bph = Wh; Bpl = Wl; nb = n0; ldb = FF; }
    else if (mode == 2) { Bph = Wh + (size_t)roi * RD * D; Bpl = Wl + (size_t)roi * RD * D; nb = n0; ldb = D; }
    else                { Bph = Wh; Bpl = Wl; nb = n0; ldb = D; }

    if (mode == 2) {
        Ah += (size_t)roi * BATCH * XPAD;
        Al += (size_t)roi * BATCH * XPAD;
    }

    float acc[2][4][4] = {};

    for (int k0 = 0; k0 < K; k0 += 32) {
#pragma unroll
        for (int p = t; p < 1024; p += 256) {
            int row = p >> 3, c4 = (p & 7) * 4;
            size_t off = (size_t)(m0 + row) * lda + k0 + c4;
            *(uint2*)&AsH[row][c4] = *(const uint2*)(Ah + off);
            *(uint2*)&AsL[row][c4] = *(const uint2*)(Al + off);
        }
#pragma unroll
        for (int p = t; p < 512; p += 256) {
            int k = p >> 4, n4 = (p & 15) * 4;
            uint2 zh = make_uint2(0u, 0u), zl = make_uint2(0u, 0u);
            if (k0 + k < K) {
                size_t off = (size_t)(k0 + k) * ldb + nb + n4;
                zh = *(const uint2*)(Bph + off);
                zl = *(const uint2*)(Bpl + off);
            }
            *(uint2*)&BsH[k][n4] = zh;
            *(uint2*)&BsL[k][n4] = zl;
        }
        __syncthreads();

#pragma unroll
        for (int ks = 0; ks < 2; ++ks) {
            int kb = ks * 16;
            unsigned aH[2][4], aL[2][4];
            int aro = ((lane >> 3) & 1) * 8 + (lane & 7);
            int aco = kb + (lane >> 4) * 8;
#pragma unroll
            for (int mt = 0; mt < 2; ++mt) {
                int r = wm * 32 + mt * 16 + aro;
                ldsm_x4(smem_u32(&AsH[r][aco]), aH[mt][0], aH[mt][1], aH[mt][2], aH[mt][3]);
                ldsm_x4(smem_u32(&AsL[r][aco]), aL[mt][0], aL[mt][1], aL[mt][2], aL[mt][3]);
            }
            unsigned bH[4][2], bL[4][2];
            int bro = kb + ((lane >> 3) & 1) * 8 + (lane & 7);
            int bco = wn * 32 + (lane >> 4) * 8;
#pragma unroll
            for (int np = 0; np < 2; ++np) {
                unsigned r0, r1, r2, r3;
                ldsm_x4t(smem_u32(&BsH[bro][bco + np * 16]), r0, r1, r2, r3);
                bH[np*2][0] = r0; bH[np*2][1] = r1; bH[np*2+1][0] = r2; bH[np*2+1][1] = r3;
                ldsm_x4t(smem_u32(&BsL[bro][bco + np * 16]), r0, r1, r2, r3);
                bL[np*2][0] = r0; bL[np*2][1] = r1; bL[np*2+1][0] = r2; bL[np*2+1][1] = r3;
            }
#pragma unroll
            for (int mt = 0; mt < 2; ++mt)
#pragma unroll
                for (int nt = 0; nt < 4; ++nt) {
                    mma16816(acc[mt][nt], aH[mt], bH[nt]);
                    mma16816(acc[mt][nt], aH[mt], bL[nt]);
                    mma16816(acc[mt][nt], aL[mt], bH[nt]);
                }
        }
        __syncthreads();
    }

    // ---- epilogue ----
    int g = lane >> 2, tq = (lane & 3) * 2;
#pragma unroll
    for (int mt = 0; mt < 2; ++mt) {
        int r0 = m0 + wm * 32 + mt * 16 + g;
#pragma unroll
        for (int nt = 0; nt < 4; ++nt) {
            float* c = acc[mt][nt];
            if (mode == 0) {
                int wh = n0 / D;
                int colq = nb + wn * 32 + nt * 8 + tq;
                int hd = colq >> 5, dh = colq & 31;
                float2 bb = *(const float2*)(bias + wh * D + colq);
                float* o = (wh == 0) ? oq : ((wh == 1) ? ok : ov);
                int m = r0;
                int b = m / S, s = m - b * S;
                *(float2*)(o + (((size_t)b * NH + hd) * S + s) * DH + dh)
                    = make_float2(c[0] + bb.x, c[1] + bb.y);
                m = r0 + 8; b = m / S; s = m - b * S;
                *(float2*)(o + (((size_t)b * NH + hd) * S + s) * DH + dh)
                    = make_float2(c[2] + bb.x, c[3] + bb.y);
            } else if (mode == 4) {
                int wh = n0 / D;
                int colq = nb + wn * 32 + nt * 8 + tq;
                int hd = colq >> 5, dh = colq & 31;
                float2 bb = *(const float2*)(bias + wh * D + colq);
#pragma unroll
                for (int rr = 0; rr < 2; ++rr) {
                    int m = r0 + rr * 8;
                    int b = m / S, s = m - b * S;
                    int bhq = b * NH + hd;
                    float f0 = c[rr * 2 + 0] + bb.x;
                    float f1 = c[rr * 2 + 1] + bb.y;
                    bf16 h0, l0, h1, l1;
                    if (wh == 0) {
                        f0 *= 0.17677669529663687f; f1 *= 0.17677669529663687f;
                        split_bf(f0, h0, l0); split_bf(f1, h1, l1);
                        size_t off = ((size_t)bhq * S + s) * DH + dh;
                        *(__nv_bfloat162*)(xqh + off) = __nv_bfloat162(h0, h1);
                        *(__nv_bfloat162*)(xql + off) = __nv_bfloat162(l0, l1);
                    } else if (wh == 1) {
                        split_bf(f0, h0, l0); split_bf(f1, h1, l1);
                        size_t off = ((size_t)bhq * DH + dh) * S + s;
                        xkh[off] = h0; xkh[off + S] = h1;
                        xkl[off] = l0; xkl[off + S] = l1;
                    } else {
                        split_bf(f0, h0, l0); split_bf(f1, h1, l1);
                        size_t off = ((size_t)bhq * S + s) * DH + dh;
                        *(__nv_bfloat162*)(xvh + off) = __nv_bfloat162(h0, h1);
                        *(__nv_bfloat162*)(xvl + off) = __nv_bfloat162(l0, l1);
                    }
                }
            } else if (mode == 1) {
                int col = n0 + wn * 32 + nt * 8 + tq;
                float2 bb = *(const float2*)(bias + col);
                float f0 = gelu_exact(c[0] + bb.x), f1 = gelu_exact(c[1] + bb.y);
                bf16 h0, l0, h1, l1;
                split_bf(f0, h0, l0); split_bf(f1, h1, l1);
                *(__nv_bfloat162*)(obh + (size_t)r0 * FF + col) = __nv_bfloat162(h0, h1);
                *(__nv_bfloat162*)(obl + (size_t)r0 * FF + col) = __nv_bfloat162(l0, l1);
                f0 = gelu_exact(c[2] + bb.x); f1 = gelu_exact(c[3] + bb.y);
                split_bf(f0, h0, l0); split_bf(f1, h1, l1);
                *(__nv_bfloat162*)(obh + (size_t)(r0 + 8) * FF + col) = __nv_bfloat162(h0, h1);
                *(__nv_bfloat162*)(obl + (size_t)(r0 + 8) * FF + col) = __nv_bfloat162(l0, l1);
            } else if (mode == 2) {
                int col = n0 + wn * 32 + nt * 8 + tq;
                float2 bb = *(const float2*)(bias + (size_t)roi * D + col);
                *(float2*)(of + ((size_t)r0 * S + roi) * D + col)
                    = make_float2(c[0] + bb.x, c[1] + bb.y);
                *(float2*)(of + ((size_t)(r0 + 8) * S + roi) * D + col)
                    = make_float2(c[2] + bb.x, c[3] + bb.y);
            } else {
                int col = n0 + wn * 32 + nt * 8 + tq;
                float2 bb = *(const float2*)(bias + col);
                *(float2*)(of + (size_t)r0 * D + col)
                    = make_float2(c[0] + bb.x, c[1] + bb.y);
                *(float2*)(of + (size_t)(r0 + 8) * D + col)
                    = make_float2(c[2] + bb.x, c[3] + bb.y);
            }
        }
    }
}

// ============================================================================
// Tensor-core attention. CTA per (b,h), 8 warps. Queries padded to 208
// (13 m16 tiles; warp w owns tile w, plus tile w+8 if w<5). Keys streamed in
// 32-key tiles (7 tiles, masked past 200). All smem rows padded to 40 elems
// (80 B, 16B-aligned for ldmatrix). bf16x3 scores + PV; one-pass softmax.
// ============================================================================
__global__ __launch_bounds__(256, 2) void attn_mma_kernel(
    const bf16* __restrict__ qbh, const bf16* __restrict__ qbl,
    const bf16* __restrict__ kth, const bf16* __restrict__ ktl,
    const bf16* __restrict__ vbh, const bf16* __restrict__ vbl,
    bf16* __restrict__ oh, bf16* __restrict__ ol)
{
    __shared__ bf16 Qh[208][40], Ql[208][40];
    __shared__ bf16 Kh[32][40],  Kl[32][40];
    __shared__ bf16 Vh[32][40],  Vl[32][40];

    int bh = blockIdx.x;
    int b = bh / NH, hd = bh - b * NH;
    int t = threadIdx.x, warp = t >> 5, lane = t & 31;
    int g = lane >> 2, tq = lane & 3;

    // load Q (zero-padded rows 200..207)
    const unsigned* qhp = (const unsigned*)(qbh + (size_t)bh * S * DH);
    const unsigned* qlp = (const unsigned*)(qbl + (size_t)bh * S * DH);
    for (int i = t; i < 208 * 16; i += 256) {
        int row = i >> 4, cp = i & 15;
        unsigned a = 0, c = 0;
        if (row < S) { a = qhp[row * 16 + cp]; c = qlp[row * 16 + cp]; }
        *(unsigned*)&Qh[row][cp * 2] = a;
        *(unsigned*)&Ql[row][cp * 2] = c;
    }
    __syncthreads();

    int nmt = (warp < 5) ? 2 : 1;
    int mt0 = warp * 16, mt1 = (8 + warp) * 16;

    int aro  = ((lane >> 3) & 1) * 8 + (lane & 7);
    int acoh = (lane >> 4) * 8;

    // hoist Q fragments (loop-invariant over key tiles)
    unsigned qH[2][2][4], qL[2][2][4];
    for (int mi = 0; mi < nmt; ++mi) {
        int mrow = mi ? mt1 : mt0;
#pragma unroll
        for (int ks = 0; ks < 2; ++ks) {
            ldsm_x4(smem_u32(&Qh[mrow + aro][ks * 16 + acoh]),
                    qH[mi][ks][0], qH[mi][ks][1], qH[mi][ks][2], qH[mi][ks][3]);
            ldsm_x4(smem_u32(&Ql[mrow + aro][ks * 16 + acoh]),
                    qL[mi][ks][0], qL[mi][ks][1], qL[mi][ks][2], qL[mi][ks][3]);
        }
    }

    float oacc[2][4][4] = {};
    float lsum[2][2] = {};

    const bf16* khb = kth + (size_t)bh * DH * S;
    const bf16* klb = ktl + (size_t)bh * DH * S;
    const unsigned* vhp = (const unsigned*)(vbh + (size_t)bh * S * DH);
    const unsigned* vlp = (const unsigned*)(vbl + (size_t)bh * S * DH);

    for (int kt = 0; kt < 7; ++kt) {
        int kt0 = kt * 32;
        __syncthreads();
        // K tile: rows = dh (32), cols = 32 keys (pairs)
        for (int i = t; i < 512; i += 256) {
            int row = i >> 4, cp = i & 15;
            int key = kt0 + cp * 2;
            unsigned a = 0, c = 0;
            if (key < S) {
                a = *(const unsigned*)(khb + row * S + key);
                c = *(const unsigned*)(klb + row * S + key);
            }
            *(unsigned*)&Kh[row][cp * 2] = a;
            *(unsigned*)&Kl[row][cp * 2] = c;
        }
        // V tile: rows = 32 keys, cols = dh (pairs)
        for (int i = t; i < 512; i += 256) {
            int row = i >> 4, cp = i & 15;
            int key = kt0 + row;
            unsigned a = 0, c = 0;
            if (key < S) { a = vhp[key * 16 + cp]; c = vlp[key * 16 + cp]; }
            *(unsigned*)&Vh[row][cp * 2] = a;
            *(unsigned*)&Vl[row][cp * 2] = c;
        }
        __syncthreads();

        for (int mi = 0; mi < nmt; ++mi) {
#pragma unroll
            for (int kg = 0; kg < 2; ++kg) {
                float sc2[2][4] = {};
#pragma unroll
                for (int ks = 0; ks < 2; ++ks) {
                    unsigned kh2[2][2], kl2[2][2], r0, r1, r2, r3;
                    ldsm_x4t(smem_u32(&Kh[ks * 16 + aro][kg * 16 + acoh]), r0, r1, r2, r3);
                    kh2[0][0] = r0; kh2[0][1] = r1; kh2[1][0] = r2; kh2[1][1] = r3;
                    ldsm_x4t(smem_u32(&Kl[ks * 16 + aro][kg * 16 + acoh]), r0, r1, r2, r3);
                    kl2[0][0] = r0; kl2[0][1] = r1; kl2[1][0] = r2; kl2[1][1] = r3;
#pragma unroll
                    for (int j = 0; j < 2; ++j) {
                        mma16816(sc2[j], qH[mi][ks], kh2[j]);
                        mma16816(sc2[j], qH[mi][ks], kl2[j]);
                        mma16816(sc2[j], qL[mi][ks], kh2[j]);
                    }
                }
                // exp + mask + l accumulation
                float e[8];
#pragma unroll
                for (int j = 0; j < 2; ++j) {
                    int keyb = kt0 + (kg * 2 + j) * 8 + tq * 2;
                    float e0 = __expf(sc2[j][0]);
                    float e1 = __expf(sc2[j][1]);
                    float e2 = __expf(sc2[j][2]);
                    float e3 = __expf(sc2[j][3]);
                    if (keyb >= S)     { e0 = 0.f; e2 = 0.f; }
                    if (keyb + 1 >= S) { e1 = 0.f; e3 = 0.f; }
                    lsum[mi][0] += e0 + e1;
                    lsum[mi][1] += e2 + e3;
                    e[j * 4 + 0] = e0; e[j * 4 + 1] = e1;
                    e[j * 4 + 2] = e2; e[j * 4 + 3] = e3;
                }
                // P as A-frag (C->A register identity), split hi/lo
                unsigned paH[4], paL[4];
                {
                    bf16 h0, l0, h1, l1;
                    split_bf(e[0], h0, l0); split_bf(e[1], h1, l1);
                    paH[0] = pack_bf2(h0, h1); paL[0] = pack_bf2(l0, l1);
                    split_bf(e[2], h0, l0); split_bf(e[3], h1, l1);
                    paH[1] = pack_bf2(h0, h1); paL[1] = pack_bf2(l0, l1);
                    split_bf(e[4], h0, l0); split_bf(e[5], h1, l1);
                    paH[2] = pack_bf2(h0, h1); paL[2] = pack_bf2(l0, l1);
                    split_bf(e[6], h0, l0); split_bf(e[7], h1, l1);
                    paH[3] = pack_bf2(h0, h1); paL[3] = pack_bf2(l0, l1);
                }
                // PV: k-dim = this 16-key group
#pragma unroll
                for (int np = 0; np < 2; ++np) {
                    unsigned vh2[2][2], vl2[2][2], r0, r1, r2, r3;
                    ldsm_x4t(smem_u32(&Vh[kg * 16 + aro][np * 16 + acoh]), r0, r1, r2, r3);
                    vh2[0][0] = r0; vh2[0][1] = r1; vh2[1][0] = r2; vh2[1][1] = r3;
                    ldsm_x4t(smem_u32(&Vl[kg * 16 + aro][np * 16 + acoh]), r0, r1, r2, r3);
                    vl2[0][0] = r0; vl2[0][1] = r1; vl2[1][0] = r2; vl2[1][1] = r3;
#pragma unroll
                    for (int j = 0; j < 2; ++j) {
                        int n8 = np * 2 + j;
                        mma16816(oacc[mi][n8], paH, vh2[j]);
                        mma16816(oacc[mi][n8], paH, vl2[j]);
                        mma16816(oacc[mi][n8], paL, vh2[j]);
                    }
                }
            }
        }
    }

    // finalize: reduce l over quad, scale, store bf16 hi/lo
    for (int mi = 0; mi < nmt; ++mi) {
        float l0 = lsum[mi][0], l1 = lsum[mi][1];
        l0 += __shfl_xor_sync(0xffffffffu, l0, 1);
        l0 += __shfl_xor_sync(0xffffffffu, l0, 2);
        l1 += __shfl_xor_sync(0xffffffffu, l1, 1);
        l1 += __shfl_xor_sync(0xffffffffu, l1, 2);
        float i0 = 1.f / l0, i1 = 1.f / l1;
        int mrow = mi ? mt1 : mt0;
        int s0 = mrow + g;
#pragma unroll
        for (int n8 = 0; n8 < 4; ++n8) {
            int col = hd * DH + n8 * 8 + tq * 2;
            if (s0 < S) {
                float f0 = oacc[mi][n8][0] * i0, f1 = oacc[mi][n8][1] * i0;
                bf16 h0, lo0, h1, lo1;
                split_bf(f0, h0, lo0); split_bf(f1, h1, lo1);
                size_t off = ((size_t)b * S + s0) * D + col;
                *(__nv_bfloat162*)(oh + off) = __nv_bfloat162(h0, h1);
                *(__nv_bfloat162*)(ol + off) = __nv_bfloat162(lo0, lo1);
            }
            if (s0 + 8 < S) {
                float f0 = oacc[mi][n8][2] * i1, f1 = oacc[mi][n8][3] * i1;
                bf16 h0, lo0, h1, lo1;
                split_bf(f0, h0, lo0); split_bf(f1, h1, lo1);
                size_t off = ((size_t)b * S + s0 + 8) * D + col;
                *(__nv_bfloat162*)(oh + off) = __nv_bfloat162(h0, h1);
                *(__nv_bfloat162*)(ol + off) = __nv_bfloat162(lo0, lo1);
            }
        }
    }
}

// ============================================================================
// add + LayerNorm: out = LN(raw + res) -> fp32 h + bf16 hi/lo
// ============================================================================
__global__ void addln_kernel(const float* __restrict__ raw,
                             const float* __restrict__ res,
                             const float* __restrict__ lng,
                             const float* __restrict__ lnb,
                             float* __restrict__ out,
                             bf16* __restrict__ oh, bf16* __restrict__ ol)
{
    int row = blockIdx.x * 8 + (threadIdx.x >> 5);
    int lane = threadIdx.x & 31;
    float vv[6];
    float sum = 0.f, sq = 0.f;
#pragma unroll
    for (int j = 0; j < 6; ++j) {
        int c = lane + 32 * j;
        vv[j] = raw[(size_t)row * D + c] + res[(size_t)row * D + c];
        sum += vv[j]; sq += vv[j] * vv[j];
    }
#pragma unroll
    for (int o = 16; o > 0; o >>= 1) {
        sum += __shfl_xor_sync(0xffffffffu, sum, o);
        sq  += __shfl_xor_sync(0xffffffffu, sq,  o);
    }
    float mean = sum * (1.f / D);
    float rstd = rsqrtf(sq * (1.f / D) - mean * mean + 1e-5f);
#pragma unroll
    for (int j = 0; j < 6; ++j) {
        int c = lane + 32 * j;
        float val = (vv[j] - mean) * rstd * lng[c] + lnb[c];
        out[(size_t)row * D + c] = val;
        bf16 h, l; split_bf(val, h, l);
        oh[(size_t)row * D + c] = h; ol[(size_t)row * D + c] = l;
    }
}

// ============================================================================
// token epilogue: per-roi LN + GELU + pos -> fp32 h + bf16 hi/lo
// ============================================================================
__global__ void tok_finish_kernel(const float* __restrict__ raw,
                                  const float* __restrict__ lng,
                                  const float* __restrict__ lnb,
                                  const float* __restrict__ pos,
                                  float* __restrict__ out,
                                  bf16* __restrict__ oh, bf16* __restrict__ ol)
{
    int row = blockIdx.x * 8 + (threadIdx.x >> 5);
    int roi = row % S;
    int lane = threadIdx.x & 31;
    float vv[6];
    float sum = 0.f, sq = 0.f;
#pragma unroll
    for (int j = 0; j < 6; ++j) {
        vv[j] = raw[(size_t)row * D + lane + 32 * j];
        sum += vv[j]; sq += vv[j] * vv[j];
    }
#pragma unroll
    for (int o = 16; o > 0; o >>= 1) {
        sum += __shfl_xor_sync(0xffffffffu, sum, o);
        sq  += __shfl_xor_sync(0xffffffffu, sq,  o);
    }
    float mean = sum * (1.f / D);
    float rstd = rsqrtf(sq * (1.f / D) - mean * mean + 1e-5f);
#pragma unroll
    for (int j = 0; j < 6; ++j) {
        int c = lane + 32 * j;
        float v = (vv[j] - mean) * rstd * lng[(size_t)roi * D + c] + lnb[(size_t)roi * D + c];
        float val = gelu_exact(v) + pos[(size_t)roi * D + c];
        out[(size_t)row * D + c] = val;
        bf16 h, l; split_bf(val, h, l);
        oh[(size_t)row * D + c] = h; ol[(size_t)row * D + c] = l;
    }
}

// ---------------- pooled attention (Q=1 via linearity) ---------------------
__global__ void pool_attn_kernel(const float* __restrict__ q,
                                 const float* __restrict__ k,
                                 const float* __restrict__ v,
                                 float* __restrict__ out)
{
    __shared__ float qm[DH];
    __shared__ float sc[S];
    __shared__ float red[2];
    int bh = blockIdx.x;
    int b = bh / NH, hd = bh % NH;
    size_t base = (size_t)bh * S * DH;
    int t = threadIdx.x;
    if (t < DH) {
        float s = 0.f;
        for (int j = 0; j < S; ++j) s += q[base + j * DH + t];
        qm[t] = s * (1.f / S) * 0.17677669529663687f;
    }
    __syncthreads();
    if (t < S) {
        float x = 0.f;
#pragma unroll
        for (int i = 0; i < DH; ++i) x += qm[i] * k[base + t * DH + i];
        sc[t] = x;
    }
    __syncthreads();
    if (t == 0) {
        float mx = -1e30f;
        for (int s = 0; s < S; ++s) mx = fmaxf(mx, sc[s]);
        red[0] = mx;
    }
    __syncthreads();
    if (t < S) sc[t] = __expf(sc[t] - red[0]);
    __syncthreads();
    if (t == 0) {
        float l = 0.f;
        for (int s = 0; s < S; ++s) l += sc[s];
        red[1] = 1.f / l;
    }
    __syncthreads();
    if (t < DH) {
        float o = 0.f;
        for (int s = 0; s < S; ++s) o += sc[s] * v[base + s * DH + t];
        out[(size_t)b * D + hd * DH + t] = o * red[1];
    }
}

// ---------------- pooled projection ----------------------------------------
__global__ void pool_proj_kernel(const float* __restrict__ in,
                                 const float* __restrict__ W,
                                 const float* __restrict__ bias,
                                 float* __restrict__ out)
{
    __shared__ float row[D];
    int b = blockIdx.x, d = threadIdx.x;
    row[d] = in[(size_t)b * D + d];
    __syncthreads();
    float s = bias[d];
    for (int k = 0; k < D; ++k) s += row[k] * W[(size_t)k * D + d];
    out[(size_t)b * D + d] = s;
}

// ---------------- classifier head ------------------------------------------
__global__ void cls_kernel(const float* __restrict__ in,
                           const float* __restrict__ g,  const float* __restrict__ bt,
                           const float* __restrict__ W1, const float* __restrict__ b1,
                           const float* __restrict__ W2, const float* __restrict__ b2,
                           const float* __restrict__ W3, const float* __restrict__ b3,
                           float* __restrict__ out)
{
    __shared__ float z[D];
    __shared__ float z1[96];
    __shared__ float z2[48];
    __shared__ float red[2];
    int b = blockIdx.x, t = threadIdx.x;
    float v = in[(size_t)b * D + t];
    z[t] = v;
    __syncthreads();
    if (t == 0) {
        float s = 0.f, sq = 0.f;
        for (int i = 0; i < D; ++i) { s += z[i]; sq += z[i] * z[i]; }
        float m = s / D;
        red[0] = m;
        red[1] = rsqrtf(sq / D - m * m + 1e-5f);
    }
    __syncthreads();
    z[t] = (v - red[0]) * red[1] * g[t] + bt[t];
    __syncthreads();
    if (t < 96) {
        float a = b1[t];
        for (int k = 0; k < D; ++k) a += z[k] * W1[k * 96 + t];
        z1[t] = gelu_exact(a);
    }
    __syncthreads();
    if (t < 48) {
        float a = b2[t];
        for (int k = 0; k < 96; ++k) a += z1[k] * W2[k * 48 + t];
        z2[t] = gelu_exact(a);
    }
    __syncthreads();
    if (t < 2) {
        float a = b3[t];
        for (int k = 0; k < 48; ++k) a += z2[k] * W3[k * 2 + t];
        out[(size_t)b * 2 + t] = a;
    }
}

// ---------------- launch ----------------------------------------------------
extern "C" void kernel_launch(void* const* d_in, const int* in_sizes, int n_in,
                              void* d_out, int out_size)
{
    const float* x        = (const float*)d_in[0];
    const float* roi_W    = (const float*)d_in[1];
    const float* roi_b    = (const float*)d_in[2];
    const float* roi_lng  = (const float*)d_in[3];
    const float* roi_lnb  = (const float*)d_in[4];
    const float* pos_emb  = (const float*)d_in[5];
    const float* enc_Wqkv = (const float*)d_in[6];
    const float* enc_bqkv = (const float*)d_in[7];
    const float* enc_Wo   = (const float*)d_in[8];
    const float* enc_bo   = (const float*)d_in[9];
    const float* enc_ln1g = (const float*)d_in[10];
    const float* enc_ln1b = (const float*)d_in[11];
    const float* enc_W1   = (const float*)d_in[12];
    const float* enc_b1   = (const float*)d_in[13];
    const float* enc_W2   = (const float*)d_in[14];
    const float* enc_b2   = (const float*)d_in[15];
    const float* enc_ln2g = (const float*)d_in[16];
    const float* enc_ln2b = (const float*)d_in[17];
    const float* pool_Wqkv= (const float*)d_in[18];
    const float* pool_bqkv= (const float*)d_in[19];
    const float* pool_Wo  = (const float*)d_in[20];
    const float* pool_bo  = (const float*)d_in[21];
    const float* cls_lng  = (const float*)d_in[22];
    const float* cls_lnb  = (const float*)d_in[23];
    const float* cls_W1   = (const float*)d_in[24];
    const float* cls_b1   = (const float*)d_in[25];
    const float* cls_W2   = (const float*)d_in[26];
    const float* cls_b2   = (const float*)d_in[27];
    const float* cls_W3   = (const float*)d_in[28];
    const float* cls_b3   = (const float*)d_in[29];
    float* out = (float*)d_out;

    float *h, *raw, *q, *k, *v, *pool, *pooled;
    bf16 *xh, *xl, *hh, *hl, *ah, *al, *fh, *fl;
    bf16 *qbh, *qbl, *kth, *ktl, *vbh, *vbl;
    bf16 *rwh, *rwl, *qkvh, *qkvl, *woh, *wol, *w1h, *w1l, *w2h, *w2l, *pwh, *pwl;
    cudaGetSymbolAddress((void**)&h,    g_h);
    cudaGetSymbolAddress((void**)&raw,  g_raw);
    cudaGetSymbolAddress((void**)&q,    g_q);
    cudaGetSymbolAddress((void**)&k,    g_k);
    cudaGetSymbolAddress((void**)&v,    g_v);
    cudaGetSymbolAddress((void**)&pool, g_pool);
    cudaGetSymbolAddress((void**)&pooled, g_pooled);
    cudaGetSymbolAddress((void**)&xh, g_xh);   cudaGetSymbolAddress((void**)&xl, g_xl);
    cudaGetSymbolAddress((void**)&hh, g_hh);   cudaGetSymbolAddress((void**)&hl, g_hl);
    cudaGetSymbolAddress((void**)&ah, g_ah);   cudaGetSymbolAddress((void**)&al, g_al);
    cudaGetSymbolAddress((void**)&fh, g_fh);   cudaGetSymbolAddress((void**)&fl, g_fl);
    cudaGetSymbolAddress((void**)&qbh, g_qbh); cudaGetSymbolAddress((void**)&qbl, g_qbl);
    cudaGetSymbolAddress((void**)&kth, g_kth); cudaGetSymbolAddress((void**)&ktl, g_ktl);
    cudaGetSymbolAddress((void**)&vbh, g_vbh); cudaGetSymbolAddress((void**)&vbl, g_vbl);
    cudaGetSymbolAddress((void**)&rwh, g_rwh); cudaGetSymbolAddress((void**)&rwl, g_rwl);
    cudaGetSymbolAddress((void**)&qkvh, g_qkvh); cudaGetSymbolAddress((void**)&qkvl, g_qkvl);
    cudaGetSymbolAddress((void**)&woh, g_woh); cudaGetSymbolAddress((void**)&wol, g_wol);
    cudaGetSymbolAddress((void**)&w1h, g_w1h); cudaGetSymbolAddress((void**)&w1l, g_w1l);
    cudaGetSymbolAddress((void**)&w2h, g_w2h); cudaGetSymbolAddress((void**)&w2l, g_w2l);
    cudaGetSymbolAddress((void**)&pwh, g_pwh); cudaGetSymbolAddress((void**)&pwl, g_pwl);

    // ---- pre-split weights & x ----
    cvt_x_kernel<<<(200 * BATCH * XPAD + 255) / 256, 256>>>(x, xh, xl);
    cvt_kernel<<<(200 * RD * D + 255) / 256, 256>>>(roi_W, rwh, rwl, 200 * RD * D);
    cvt_kernel<<<(NL * 3 * D * D + 255) / 256, 256>>>(enc_Wqkv, qkvh, qkvl, NL * 3 * D * D);
    cvt_kernel<<<(NL * D * D + 255) / 256, 256>>>(enc_Wo, woh, wol, NL * D * D);
    cvt_kernel<<<(NL * D * FF + 255) / 256, 256>>>(enc_W1, w1h, w1l, NL * D * FF);
    cvt_kernel<<<(NL * FF * D + 255) / 256, 256>>>(enc_W2, w2h, w2l, NL * FF * D);
    cvt_kernel<<<(3 * D * D + 255) / 256, 256>>>(pool_Wqkv, pwh, pwl, 3 * D * D);

    // ---- tokenizer ----
    mma_gemm_kernel<<<dim3(2, 3, 200), 256>>>(xh, xl, rwh, rwl, roi_b,
        nullptr, nullptr, nullptr, raw, nullptr, nullptr,
        nullptr, nullptr, nullptr, nullptr, nullptr, nullptr, 2, RD, XPAD);
    tok_finish_kernel<<<MTOT / 8, 256>>>(raw, roi_lng, roi_lnb, pos_emb, h, hh, hl);

    // ---- encoder layers ----
    for (int l = 0; l < NL; ++l) {
        mma_gemm_kernel<<<dim3(MTOT / 128, 9, 1), 256>>>(hh, hl,
            qkvh + (size_t)l * 3 * D * D, qkvl + (size_t)l * 3 * D * D,
            enc_bqkv + (size_t)l * 3 * D,
            nullptr, nullptr, nullptr, nullptr, nullptr, nullptr,
            qbh, qbl, kth, ktl, vbh, vbl, 4, D, D);
        attn_mma_kernel<<<BATCH * NH, 256>>>(qbh, qbl, kth, ktl, vbh, vbl, ah, al);
        mma_gemm_kernel<<<dim3(MTOT / 128, 3, 1), 256>>>(ah, al,
            woh + (size_t)l * D * D, wol + (size_t)l * D * D, enc_bo + l * D,
            nullptr, nullptr, nullptr, raw, nullptr, nullptr,
            nullptr, nullptr, nullptr, nullptr, nullptr, nullptr, 3, D, D);
        addln_kernel<<<MTOT / 8, 256>>>(raw, h, enc_ln1g + l * D, enc_ln1b + l * D, h, hh, hl);
        mma_gemm_kernel<<<dim3(MTOT / 128, 9, 1), 256>>>(hh, hl,
            w1h + (size_t)l * D * FF, w1l + (size_t)l * D * FF, enc_b1 + l * FF,
            nullptr, nullptr, nullptr, nullptr, fh, fl,
            nullptr, nullptr, nullptr, nullptr, nullptr, nullptr, 1, D, D);
        mma_gemm_kernel<<<dim3(MTOT / 128, 3, 1), 256>>>(fh, fl,
            w2h + (size_t)l * FF * D, w2l + (size_t)l * FF * D, enc_b2 + l * D,
            nullptr, nullptr, nullptr, raw, nullptr, nullptr,
            nullptr, nullptr, nullptr, nullptr, nullptr, nullptr, 3, FF, FF);
        addln_kernel<<<MTOT / 8, 256>>>(raw, h, enc_ln2g + l * D, enc_ln2b + l * D, h, hh, hl);
    }

    // ---- pooling (fp32 QKV path) ----
    mma_gemm_kernel<<<dim3(MTOT / 128, 9, 1), 256>>>(hh, hl, pwh, pwl, pool_bqkv,
        q, k, v, nullptr, nullptr, nullptr,
        nullptr, nullptr, nullptr, nullptr, nullptr, nullptr, 0, D, D);
    pool_attn_kernel<<<BATCH * NH, 256>>>(q, k, v, pool);
    pool_proj_kernel<<<BATCH, 192>>>(pool, pool_Wo, pool_bo, pooled);

    // ---- classifier ----
    cls_kernel<<<BATCH, 192>>>(pooled, cls_lng, cls_lnb, cls_W1, cls_b1,
                               cls_W2, cls_b2, cls_W3, cls_b3, out);
}